// round 3
// baseline (speedup 1.0000x reference)
#include <cuda_runtime.h>

#define NN 100000
#define D  256
#define NE 1600000
#define CAP 128
#define MAXOVF 65536

// ---------------- scratch (device globals: allocations are forbidden) -------
__device__ float g_agg[(size_t)NN * D];
__device__ float g_h1 [(size_t)NN * D];
__device__ float g_h2 [(size_t)NN * D];
__device__ int   g_cnt[NN];
__device__ int   g_srclist[(size_t)NN * CAP];
__device__ int   g_ovf[2 * MAXOVF];
__device__ int   g_novf;
__device__ int   g_is64;

// ---------------- small utility kernels -------------------------------------
__global__ void zero_int_kernel(int* __restrict__ p, int n) {
    int i = blockIdx.x * blockDim.x + threadIdx.x;
    if (i < n) p[i] = 0;
}

// Probe edge-index dtype: int64 little-endian node ids (<2^31) have all odd
// 32-bit words == 0; for int32 data the odd words are random node ids.
__global__ void probe_kernel(const int* __restrict__ w) {
    if (threadIdx.x == 0) {
        int all_zero = 1;
        for (int i = 1; i < 128; i += 2)
            if (w[i] != 0) { all_zero = 0; break; }
        g_is64 = all_zero;
        g_novf = 0;
    }
}

// ---------------- bucket build ----------------------------------------------
__global__ void build_kernel(const int* __restrict__ w) {
    int e = blockIdx.x * blockDim.x + threadIdx.x;
    if (e >= NE) return;
    int s, d;
    if (g_is64) { s = w[2 * e]; d = w[2 * (NE + e)]; }
    else        { s = w[e];     d = w[NE + e];       }
    int pos = atomicAdd(&g_cnt[d], 1);
    if (pos < CAP) {
        g_srclist[(size_t)d * CAP + pos] = s;
    } else {
        int o = atomicAdd(&g_novf, 1);
        if (o < MAXOVF) { g_ovf[2 * o] = s; g_ovf[2 * o + 1] = d; }
    }
}

// ---------------- gather aggregation: agg[n] = mean over in-edges -----------
// One warp per node; each lane owns 2 float4 slots of the 256-float row.
__global__ __launch_bounds__(256)
void aggregate_kernel(const float* __restrict__ feat) {
    int warp = (blockIdx.x * blockDim.x + threadIdx.x) >> 5;
    int lane = threadIdx.x & 31;
    if (warp >= NN) return;
    int deg = g_cnt[warp];
    const int* lst = g_srclist + (size_t)warp * CAP;

    float4 a0 = make_float4(0.f, 0.f, 0.f, 0.f);
    float4 a1 = make_float4(0.f, 0.f, 0.f, 0.f);
    int nIn = min(deg, CAP);
    for (int base = 0; base < nIn; base += 32) {
        int sv = 0;
        if (base + lane < nIn) sv = lst[base + lane];
        int cnt = min(nIn - base, 32);
#pragma unroll 4
        for (int j = 0; j < cnt; j++) {
            int sj = __shfl_sync(0xffffffffu, sv, j);
            const float4* xs = (const float4*)(feat + (size_t)sj * D);
            float4 v0 = xs[lane];
            float4 v1 = xs[lane + 32];
            a0.x += v0.x; a0.y += v0.y; a0.z += v0.z; a0.w += v0.w;
            a1.x += v1.x; a1.y += v1.y; a1.z += v1.z; a1.w += v1.w;
        }
    }
    float inv = 1.0f / fmaxf((float)deg, 1.0f);
    a0.x *= inv; a0.y *= inv; a0.z *= inv; a0.w *= inv;
    a1.x *= inv; a1.y *= inv; a1.z *= inv; a1.w *= inv;
    float4* ad = (float4*)(g_agg + (size_t)warp * D);
    ad[lane]      = a0;
    ad[lane + 32] = a1;
}

// ---------------- overflow fix (never fires for this graph, but correct) ----
__global__ void ovf_kernel(const float* __restrict__ feat) {
    int lane = threadIdx.x & 31;
    int w    = (blockIdx.x * blockDim.x + threadIdx.x) >> 5;
    int nw   = (gridDim.x * blockDim.x) >> 5;
    int n = min(g_novf, MAXOVF);
    for (int e = w; e < n; e += nw) {
        int s = g_ovf[2 * e], d = g_ovf[2 * e + 1];
        float inv = 1.0f / fmaxf((float)g_cnt[d], 1.0f);
        const float* xs = feat + (size_t)s * D;
        float* ad = g_agg + (size_t)d * D;
        for (int i = lane; i < D; i += 32) atomicAdd(ad + i, xs[i] * inv);
    }
}

// ---------------- fused dual GEMM -------------------------------------------
// C = [relu]( A1 @ W1 (+ A2 @ W2) + bias ),  A:[NN,256]  W:[256,256]  C:[NN,256]
#define BM 128
#define BN 128
#define BK 16
// 256 threads; each computes an 8x8 micro-tile.

template<bool DUAL, bool RELU>
__global__ __launch_bounds__(256, 2)
void gemm_kernel(const float* __restrict__ A1, const float* __restrict__ W1,
                 const float* __restrict__ A2, const float* __restrict__ W2,
                 const float* __restrict__ bias,
                 float* __restrict__ C) {
    __shared__ float As[BK][BM];
    __shared__ float Bs[BK][BN];

    const int t  = threadIdx.x;
    const int m0 = blockIdx.x * BM;
    const int n0 = blockIdx.y * BN;
    const int ty = t >> 4;   // 0..15 -> rows ty*8..ty*8+7
    const int tx = t & 15;   // 0..15 -> cols tx*8..tx*8+7

    float acc[8][8];
#pragma unroll
    for (int i = 0; i < 8; i++)
#pragma unroll
        for (int j = 0; j < 8; j++) acc[i][j] = 0.f;

    const int nRep = DUAL ? 2 : 1;
    for (int rep = 0; rep < nRep; rep++) {
        const float* A = rep ? A2 : A1;
        const float* W = rep ? W2 : W1;

        for (int k0 = 0; k0 < D; k0 += BK) {
            __syncthreads();
            // ---- A tile: BM x BK, stored transposed As[k][m] ----
#pragma unroll
            for (int i = 0; i < 2; i++) {
                int lin = t + i * 256;       // 512 float4 slots
                int m   = lin >> 2;          // 0..127
                int kq  = lin & 3;           // k quad
                int row = m0 + m;
                float4 v = make_float4(0.f, 0.f, 0.f, 0.f);
                if (row < NN)
                    v = *(const float4*)(A + (size_t)row * D + k0 + kq * 4);
                As[kq * 4 + 0][m] = v.x;
                As[kq * 4 + 1][m] = v.y;
                As[kq * 4 + 2][m] = v.z;
                As[kq * 4 + 3][m] = v.w;
            }
            // ---- B tile: BK x BN ----
#pragma unroll
            for (int i = 0; i < 2; i++) {
                int lin = t + i * 256;       // 512 float4 slots
                int k   = lin >> 5;          // 0..15
                int nq  = lin & 31;          // 0..31
                float4 v = *(const float4*)(W + (size_t)(k0 + k) * D + n0 + nq * 4);
                *(float4*)&Bs[k][nq * 4] = v;
            }
            __syncthreads();
            // ---- compute ----
#pragma unroll
            for (int k = 0; k < BK; k++) {
                float a[8], b[8];
                *(float4*)&a[0] = *(float4*)&As[k][ty * 8];
                *(float4*)&a[4] = *(float4*)&As[k][ty * 8 + 4];
                *(float4*)&b[0] = *(float4*)&Bs[k][tx * 8];
                *(float4*)&b[4] = *(float4*)&Bs[k][tx * 8 + 4];
#pragma unroll
                for (int i = 0; i < 8; i++)
#pragma unroll
                    for (int j = 0; j < 8; j++)
                        acc[i][j] += a[i] * b[j];
            }
        }
    }

    // ---- epilogue ----
    const int colBase = n0 + tx * 8;
    float4 bv0 = *(const float4*)(bias + colBase);
    float4 bv1 = *(const float4*)(bias + colBase + 4);
#pragma unroll
    for (int i = 0; i < 8; i++) {
        int row = m0 + ty * 8 + i;
        if (row >= NN) continue;
        float4 c0, c1;
        c0.x = acc[i][0] + bv0.x; c0.y = acc[i][1] + bv0.y;
        c0.z = acc[i][2] + bv0.z; c0.w = acc[i][3] + bv0.w;
        c1.x = acc[i][4] + bv1.x; c1.y = acc[i][5] + bv1.y;
        c1.z = acc[i][6] + bv1.z; c1.w = acc[i][7] + bv1.w;
        if (RELU) {
            c0.x = fmaxf(c0.x, 0.f); c0.y = fmaxf(c0.y, 0.f);
            c0.z = fmaxf(c0.z, 0.f); c0.w = fmaxf(c0.w, 0.f);
            c1.x = fmaxf(c1.x, 0.f); c1.y = fmaxf(c1.y, 0.f);
            c1.z = fmaxf(c1.z, 0.f); c1.w = fmaxf(c1.w, 0.f);
        }
        float* cp = C + (size_t)row * D + colBase;
        *(float4*)cp       = c0;
        *(float4*)(cp + 4) = c1;
    }
}

// ---------------- launch ----------------------------------------------------
extern "C" void kernel_launch(void* const* d_in, const int* in_sizes, int n_in,
                              void* d_out, int out_size) {
    const float* x   = (const float*)d_in[0];
    const int*   ei  = (const int*)d_in[1];   // int32 or int64 (probed)
    const float* W1l = (const float*)d_in[2];
    const float* b1  = (const float*)d_in[3];
    const float* W1r = (const float*)d_in[4];
    const float* W2l = (const float*)d_in[5];
    const float* b2  = (const float*)d_in[6];
    const float* W2r = (const float*)d_in[7];
    const float* W3  = (const float*)d_in[8];
    const float* b3  = (const float*)d_in[9];
    float* out = (float*)d_out;

    float *agg, *h1, *h2;
    int* cnt;
    cudaGetSymbolAddress((void**)&agg, g_agg);
    cudaGetSymbolAddress((void**)&h1,  g_h1);
    cudaGetSymbolAddress((void**)&h2,  g_h2);
    cudaGetSymbolAddress((void**)&cnt, g_cnt);

    dim3 gemmGrid((NN + BM - 1) / BM, D / BN);     // (782, 2)
    const int aggBlocks = (NN * 32 + 255) / 256;   // one warp per node

    // ---- build buckets (once, reused by both layers) ----
    probe_kernel<<<1, 32>>>(ei);
    zero_int_kernel<<<(NN + 255) / 256, 256>>>(cnt, NN);
    build_kernel<<<(NE + 255) / 256, 256>>>(ei);

    // ---- layer 1 ----
    aggregate_kernel<<<aggBlocks, 256>>>(x);
    ovf_kernel<<<32, 256>>>(x);
    gemm_kernel<true, true><<<gemmGrid, 256>>>(agg, W1l, x, W1r, b1, h1);

    // ---- layer 2 ----
    aggregate_kernel<<<aggBlocks, 256>>>(h1);
    ovf_kernel<<<32, 256>>>(h1);
    gemm_kernel<true, true><<<gemmGrid, 256>>>(agg, W2l, h1, W2r, b2, h2);

    // ---- head ----
    gemm_kernel<false, false><<<gemmGrid, 256>>>(h2, W3, nullptr, nullptr, b3, out);
}

// round 5
// speedup vs baseline: 1.8687x; 1.8687x over previous
#include <cuda_runtime.h>
#include <cuda_bf16.h>
#include <cstdint>

#define NN 100000
#define D  256
#define NE 1600000
#define CAP 128
#define MAXOVF 65536

typedef __nv_bfloat16 bf16;

// ---------------- scratch (device globals: allocations are forbidden) -------
__device__ float g_agg[(size_t)NN * D];       // fp32 agg (overflow fallback)
__device__ float g_h1 [(size_t)NN * D];       // fp32 h1 (layer-2 gather input)
__device__ bf16  g_xhi[(size_t)NN * D];
__device__ bf16  g_xlo[(size_t)NN * D];
__device__ bf16  g_ahi[(size_t)NN * D];
__device__ bf16  g_alo[(size_t)NN * D];
__device__ bf16  g_h1hi[(size_t)NN * D];
__device__ bf16  g_h1lo[(size_t)NN * D];
__device__ bf16  g_h2hi[(size_t)NN * D];
__device__ bf16  g_h2lo[(size_t)NN * D];
__device__ bf16  g_wthi[5 * 65536];           // transposed weights [N][K], split
__device__ bf16  g_wtlo[5 * 65536];
__device__ int   g_cnt[NN];
__device__ int   g_srclist[(size_t)NN * CAP];
__device__ int   g_ovf[2 * MAXOVF];
__device__ int   g_novf;
__device__ int   g_is64;

// ---------------- helpers ----------------------------------------------------
__device__ __forceinline__ uint32_t smem_u32(const void* p) {
    uint32_t a;
    asm("{ .reg .u64 t; cvta.to.shared.u64 t, %1; cvt.u32.u64 %0, t; }"
        : "=r"(a) : "l"(p));
    return a;
}
__device__ __forceinline__ void cp16(uint32_t dst, const void* src, int sz) {
    asm volatile("cp.async.cg.shared.global [%0], [%1], 16, %2;"
                 :: "r"(dst), "l"(src), "r"(sz) : "memory");
}
__device__ __forceinline__ void cp_commit() {
    asm volatile("cp.async.commit_group;" ::: "memory");
}
template<int N>
__device__ __forceinline__ void cp_wait() {
    asm volatile("cp.async.wait_group %0;" :: "n"(N) : "memory");
}
__device__ __forceinline__ void ldsm4(uint32_t* r, uint32_t addr) {
    asm volatile("ldmatrix.sync.aligned.m8n8.x4.shared.b16 {%0,%1,%2,%3}, [%4];"
                 : "=r"(r[0]), "=r"(r[1]), "=r"(r[2]), "=r"(r[3]) : "r"(addr));
}
__device__ __forceinline__ void mma16816(float* c, const uint32_t* a, const uint32_t* b) {
    asm volatile("mma.sync.aligned.m16n8k16.row.col.f32.bf16.bf16.f32 "
                 "{%0,%1,%2,%3}, {%4,%5,%6,%7}, {%8,%9}, {%0,%1,%2,%3};"
                 : "+f"(c[0]), "+f"(c[1]), "+f"(c[2]), "+f"(c[3])
                 : "r"(a[0]), "r"(a[1]), "r"(a[2]), "r"(a[3]),
                   "r"(b[0]), "r"(b[1]));
}
__device__ __forceinline__ uint32_t pack_bf2(float a, float b) {
    __nv_bfloat162 t = __floats2bfloat162_rn(a, b);
    return *reinterpret_cast<uint32_t*>(&t);
}
__device__ __forceinline__ void split1(float v, float& hi, float& lo) {
    bf16 h = __float2bfloat16(v);
    hi = __bfloat162float(h);
    lo = v - hi;
}

// ---------------- small utility kernels --------------------------------------
__global__ void zero_int_kernel(int* __restrict__ p, int n) {
    int i = blockIdx.x * blockDim.x + threadIdx.x;
    if (i < n) p[i] = 0;
}
__global__ void probe_kernel(const int* __restrict__ w) {
    if (threadIdx.x == 0) {
        int all_zero = 1;
        for (int i = 1; i < 128; i += 2)
            if (w[i] != 0) { all_zero = 0; break; }
        g_is64 = all_zero;
        g_novf = 0;
    }
}
__global__ void build_kernel(const int* __restrict__ w) {
    int e = blockIdx.x * blockDim.x + threadIdx.x;
    if (e >= NE) return;
    int s, d;
    if (g_is64) { s = w[2 * e]; d = w[2 * (NE + e)]; }
    else        { s = w[e];     d = w[NE + e];       }
    int pos = atomicAdd(&g_cnt[d], 1);
    if (pos < CAP) {
        g_srclist[(size_t)d * CAP + pos] = s;
    } else {
        int o = atomicAdd(&g_novf, 1);
        if (o < MAXOVF) { g_ovf[2 * o] = s; g_ovf[2 * o + 1] = d; }
    }
}
// transpose + split the 5 weight matrices: WT[m][n*256+k] = W_m[k*256+n]
__global__ void prep_weights(const float* __restrict__ W1l, const float* __restrict__ W1r,
                             const float* __restrict__ W2l, const float* __restrict__ W2r,
                             const float* __restrict__ W3) {
    int i = blockIdx.x * blockDim.x + threadIdx.x;
    if (i >= 5 * 65536) return;
    int m = i >> 16, idx = i & 65535;
    int n = idx >> 8, k = idx & 255;
    const float* W = (m == 0) ? W1l : (m == 1) ? W1r : (m == 2) ? W2l
                   : (m == 3) ? W2r : W3;
    float v = W[k * 256 + n], hi, lo;
    split1(v, hi, lo);
    g_wthi[i] = __float2bfloat16(hi);
    g_wtlo[i] = __float2bfloat16(lo);
}
__global__ void split_x_kernel(const float* __restrict__ x) {
    size_t i = (size_t)(blockIdx.x * blockDim.x + threadIdx.x) * 4;
    if (i >= (size_t)NN * D) return;
    float4 v = *(const float4*)(x + i);
    float h0, l0, h1, l1, h2, l2, h3, l3;
    split1(v.x, h0, l0); split1(v.y, h1, l1);
    split1(v.z, h2, l2); split1(v.w, h3, l3);
    *(uint2*)((bf16*)g_xhi + i) = make_uint2(pack_bf2(h0, h1), pack_bf2(h2, h3));
    *(uint2*)((bf16*)g_xlo + i) = make_uint2(pack_bf2(l0, l1), pack_bf2(l2, l3));
}

// ---------------- gather aggregation -----------------------------------------
__global__ __launch_bounds__(256)
void aggregate_kernel(const float* __restrict__ feat,
                      bf16* __restrict__ outhi, bf16* __restrict__ outlo) {
    int warp = (blockIdx.x * blockDim.x + threadIdx.x) >> 5;
    int lane = threadIdx.x & 31;
    if (warp >= NN) return;
    int deg = g_cnt[warp];
    const int* lst = g_srclist + (size_t)warp * CAP;

    float4 a0 = make_float4(0.f, 0.f, 0.f, 0.f);
    float4 a1 = make_float4(0.f, 0.f, 0.f, 0.f);
    int nIn = min(deg, CAP);
    for (int base = 0; base < nIn; base += 32) {
        int sv = 0;
        if (base + lane < nIn) sv = lst[base + lane];
        int cnt = min(nIn - base, 32);
#pragma unroll 4
        for (int j = 0; j < cnt; j++) {
            int sj = __shfl_sync(0xffffffffu, sv, j);
            const float4* xs = (const float4*)(feat + (size_t)sj * D);
            float4 v0 = xs[lane];
            float4 v1 = xs[lane + 32];
            a0.x += v0.x; a0.y += v0.y; a0.z += v0.z; a0.w += v0.w;
            a1.x += v1.x; a1.y += v1.y; a1.z += v1.z; a1.w += v1.w;
        }
    }
    float inv = 1.0f / fmaxf((float)deg, 1.0f);
    a0.x *= inv; a0.y *= inv; a0.z *= inv; a0.w *= inv;
    a1.x *= inv; a1.y *= inv; a1.z *= inv; a1.w *= inv;

    float4* ad = (float4*)(g_agg + (size_t)warp * D);
    ad[lane]      = a0;
    ad[lane + 32] = a1;

    float h, l, h2, l2, h3, l3, h4, l4;
    split1(a0.x, h, l); split1(a0.y, h2, l2); split1(a0.z, h3, l3); split1(a0.w, h4, l4);
    *(uint2*)(outhi + (size_t)warp * D + lane * 4) = make_uint2(pack_bf2(h, h2), pack_bf2(h3, h4));
    *(uint2*)(outlo + (size_t)warp * D + lane * 4) = make_uint2(pack_bf2(l, l2), pack_bf2(l3, l4));
    split1(a1.x, h, l); split1(a1.y, h2, l2); split1(a1.z, h3, l3); split1(a1.w, h4, l4);
    *(uint2*)(outhi + (size_t)warp * D + 128 + lane * 4) = make_uint2(pack_bf2(h, h2), pack_bf2(h3, h4));
    *(uint2*)(outlo + (size_t)warp * D + 128 + lane * 4) = make_uint2(pack_bf2(l, l2), pack_bf2(l3, l4));
}

__global__ void ovf_kernel(const float* __restrict__ feat) {
    int lane = threadIdx.x & 31;
    int w    = (blockIdx.x * blockDim.x + threadIdx.x) >> 5;
    int nw   = (gridDim.x * blockDim.x) >> 5;
    int n = min(g_novf, MAXOVF);
    for (int e = w; e < n; e += nw) {
        int s = g_ovf[2 * e], d = g_ovf[2 * e + 1];
        float inv = 1.0f / fmaxf((float)g_cnt[d], 1.0f);
        const float* xs = feat + (size_t)s * D;
        float* ad = g_agg + (size_t)d * D;
        for (int i = lane; i < D; i += 32) atomicAdd(ad + i, xs[i] * inv);
    }
}
__global__ void fixsplit_kernel(bf16* __restrict__ outhi, bf16* __restrict__ outlo) {
    int lane = threadIdx.x & 31;
    int w    = (blockIdx.x * blockDim.x + threadIdx.x) >> 5;
    int nw   = (gridDim.x * blockDim.x) >> 5;
    int n = min(g_novf, MAXOVF);
    for (int e = w; e < n; e += nw) {
        int d = g_ovf[2 * e + 1];
        const float* src = g_agg + (size_t)d * D;
        for (int c = lane; c < D; c += 32) {
            float hi, lo;
            split1(src[c], hi, lo);
            outhi[(size_t)d * D + c] = __float2bfloat16(hi);
            outlo[(size_t)d * D + c] = __float2bfloat16(lo);
        }
    }
}

// ---------------- mma.sync GEMM ----------------------------------------------
// CTA: 128 rows x 128 cols. 8 warps (4m x 2n), warp tile 32x64.
// C = [relu]( A1@W1' (+ A2@W2') + bias ); 3-term bf16 split per product.
// Smem stage: AH | AL | BH | BL, each 128 rows x 32 k bf16, row stride 80B.
#define ROWB   80
#define MAT_SZ 10240            // 128 * 80
#define STAGE  (4 * MAT_SZ)     // 40960
#define SMEMSZ (2 * STAGE)      // 81920

template<bool DUAL, bool RELU, bool F32OUT, bool SPLITOUT>
__global__ __launch_bounds__(256, 2)
void mma_gemm(const bf16* __restrict__ a1hi, const bf16* __restrict__ a1lo,
              const bf16* __restrict__ w1hi, const bf16* __restrict__ w1lo,
              const bf16* __restrict__ a2hi, const bf16* __restrict__ a2lo,
              const bf16* __restrict__ w2hi, const bf16* __restrict__ w2lo,
              const float* __restrict__ bias,
              float* __restrict__ Cf,
              bf16* __restrict__ Chi, bf16* __restrict__ Clo) {
    extern __shared__ char smem[];
    const uint32_t sb = smem_u32(smem);
    const int tid  = threadIdx.x;
    const int wid  = tid >> 5;
    const int lane = tid & 31;
    const int wm   = wid & 3;        // m strip: wm*32
    const int wn   = wid >> 2;       // n strip: wn*64
    const int m0   = blockIdx.x * 128;
    const int n0   = blockIdx.y * 128;

    float acc[2][8][4];
#pragma unroll
    for (int mi = 0; mi < 2; mi++)
#pragma unroll
        for (int ni = 0; ni < 8; ni++)
#pragma unroll
            for (int q = 0; q < 4; q++) acc[mi][ni][q] = 0.f;

    const int nIter = (DUAL ? 2 : 1) * 8;    // K chunks of 32

    // -------- prefetch lambda --------
    auto prefetch = [&](int buf, int it) {
        const int rep   = it >> 3;
        const int kbase = (it & 7) * 32;
        const bf16* Ah = rep ? a2hi : a1hi;
        const bf16* Al = rep ? a2lo : a1lo;
        const bf16* Wh = rep ? w2hi : w1hi;
        const bf16* Wl = rep ? w2lo : w1lo;
        const uint32_t bb = sb + buf * STAGE;
#pragma unroll
        for (int i = 0; i < 2; i++) {
            int q   = tid + i * 256;         // 0..511
            int row = q >> 2, c4 = q & 3;
            uint32_t dsto = (uint32_t)(row * ROWB + c4 * 16);
            int grow = m0 + row;
            int arow = grow < NN ? grow : 0;
            int sz   = grow < NN ? 16 : 0;
            cp16(bb + 0 * MAT_SZ + dsto, Ah + (size_t)arow * D + kbase + c4 * 8, sz);
            cp16(bb + 1 * MAT_SZ + dsto, Al + (size_t)arow * D + kbase + c4 * 8, sz);
            cp16(bb + 2 * MAT_SZ + dsto, Wh + (size_t)(n0 + row) * D + kbase + c4 * 8, 16);
            cp16(bb + 3 * MAT_SZ + dsto, Wl + (size_t)(n0 + row) * D + kbase + c4 * 8, 16);
        }
    };

    prefetch(0, 0);
    cp_commit();

    // per-lane ldmatrix address offsets
    const int alr = lane & 15, akh = lane >> 4;                 // A: row, k half
    const int bnr = lane & 7, bkh = (lane >> 3) & 1, btl = lane >> 4;  // B

    for (int it = 0; it < nIter; it++) {
        if (it + 1 < nIter) { prefetch((it + 1) & 1, it + 1); cp_commit(); cp_wait<1>(); }
        else                { cp_wait<0>(); }
        __syncthreads();

        const uint32_t bb = sb + (it & 1) * STAGE;
        const uint32_t AHb = bb, ALb = bb + MAT_SZ, BHb = bb + 2 * MAT_SZ, BLb = bb + 3 * MAT_SZ;

#pragma unroll
        for (int k16 = 0; k16 < 2; k16++) {
            const uint32_t a_off = (uint32_t)((wm * 32 + alr) * ROWB + (k16 * 16 + akh * 8) * 2);
            const uint32_t b_off = (uint32_t)((wn * 64 + btl * 8 + bnr) * ROWB + (k16 * 16 + bkh * 8) * 2);

            uint32_t ah[2][4], al[2][4], bb_[8][2];
            ldsm4(ah[0], AHb + a_off);
            ldsm4(ah[1], AHb + a_off + 16 * ROWB);
            ldsm4(al[0], ALb + a_off);
            ldsm4(al[1], ALb + a_off + 16 * ROWB);
#pragma unroll
            for (int i = 0; i < 4; i++) {
                uint32_t r[4];
                ldsm4(r, BHb + b_off + i * 16 * ROWB);
                bb_[2 * i][0] = r[0]; bb_[2 * i][1] = r[1];
                bb_[2 * i + 1][0] = r[2]; bb_[2 * i + 1][1] = r[3];
            }
            // AH*BH + AL*BH
#pragma unroll
            for (int mi = 0; mi < 2; mi++)
#pragma unroll
                for (int ni = 0; ni < 8; ni++) {
                    mma16816(acc[mi][ni], ah[mi], bb_[ni]);
                    mma16816(acc[mi][ni], al[mi], bb_[ni]);
                }
            // BL, then AH*BL
#pragma unroll
            for (int i = 0; i < 4; i++) {
                uint32_t r[4];
                ldsm4(r, BLb + b_off + i * 16 * ROWB);
                bb_[2 * i][0] = r[0]; bb_[2 * i][1] = r[1];
                bb_[2 * i + 1][0] = r[2]; bb_[2 * i + 1][1] = r[3];
            }
#pragma unroll
            for (int mi = 0; mi < 2; mi++)
#pragma unroll
                for (int ni = 0; ni < 8; ni++)
                    mma16816(acc[mi][ni], ah[mi], bb_[ni]);
        }
        __syncthreads();
    }

    // -------- epilogue --------
    const int rbase = m0 + wm * 32 + (lane >> 2);
    const int cbase = n0 + wn * 64 + (lane & 3) * 2;
#pragma unroll
    for (int ni = 0; ni < 8; ni++) {
        const int col = cbase + ni * 8;
        const float b0 = bias[col], b1 = bias[col + 1];
#pragma unroll
        for (int mi = 0; mi < 2; mi++) {
#pragma unroll
            for (int rr = 0; rr < 2; rr++) {
                int row = rbase + mi * 16 + rr * 8;
                if (row >= NN) continue;
                float v0 = acc[mi][ni][rr * 2 + 0] + b0;
                float v1 = acc[mi][ni][rr * 2 + 1] + b1;
                if (RELU) { v0 = fmaxf(v0, 0.f); v1 = fmaxf(v1, 0.f); }
                if (F32OUT)
                    *(float2*)(Cf + (size_t)row * D + col) = make_float2(v0, v1);
                if (SPLITOUT) {
                    float h0, l0, h1, l1;
                    split1(v0, h0, l0); split1(v1, h1, l1);
                    *(uint32_t*)(Chi + (size_t)row * D + col) = pack_bf2(h0, h1);
                    *(uint32_t*)(Clo + (size_t)row * D + col) = pack_bf2(l0, l1);
                }
            }
        }
    }
}

// ---------------- launch ------------------------------------------------------
extern "C" void kernel_launch(void* const* d_in, const int* in_sizes, int n_in,
                              void* d_out, int out_size) {
    const float* x   = (const float*)d_in[0];
    const int*   ei  = (const int*)d_in[1];
    const float* W1l = (const float*)d_in[2];
    const float* b1  = (const float*)d_in[3];
    const float* W1r = (const float*)d_in[4];
    const float* W2l = (const float*)d_in[5];
    const float* b2  = (const float*)d_in[6];
    const float* W2r = (const float*)d_in[7];
    const float* W3  = (const float*)d_in[8];
    const float* b3  = (const float*)d_in[9];
    float* out = (float*)d_out;

    float *h1; int* cnt;
    bf16 *xhi, *xlo, *ahi, *alo, *h1hi, *h1lo, *h2hi, *h2lo, *wthi, *wtlo;
    cudaGetSymbolAddress((void**)&h1,   g_h1);
    cudaGetSymbolAddress((void**)&cnt,  g_cnt);
    cudaGetSymbolAddress((void**)&xhi,  g_xhi);
    cudaGetSymbolAddress((void**)&xlo,  g_xlo);
    cudaGetSymbolAddress((void**)&ahi,  g_ahi);
    cudaGetSymbolAddress((void**)&alo,  g_alo);
    cudaGetSymbolAddress((void**)&h1hi, g_h1hi);
    cudaGetSymbolAddress((void**)&h1lo, g_h1lo);
    cudaGetSymbolAddress((void**)&h2hi, g_h2hi);
    cudaGetSymbolAddress((void**)&h2lo, g_h2lo);
    cudaGetSymbolAddress((void**)&wthi, g_wthi);
    cudaGetSymbolAddress((void**)&wtlo, g_wtlo);

    cudaFuncSetAttribute(mma_gemm<true,  true,  true,  true>,
                         cudaFuncAttributeMaxDynamicSharedMemorySize, SMEMSZ);
    cudaFuncSetAttribute(mma_gemm<true,  true,  false, true>,
                         cudaFuncAttributeMaxDynamicSharedMemorySize, SMEMSZ);
    cudaFuncSetAttribute(mma_gemm<false, false, true,  false>,
                         cudaFuncAttributeMaxDynamicSharedMemorySize, SMEMSZ);

    dim3 gemmGrid((NN + 127) / 128, 2);            // (782, 2)
    const int aggBlocks = (NN * 32 + 255) / 256;

    // ---- graph prep ----
    probe_kernel<<<1, 32>>>(ei);
    zero_int_kernel<<<(NN + 255) / 256, 256>>>(cnt, NN);
    build_kernel<<<(NE + 255) / 256, 256>>>(ei);
    prep_weights<<<(5 * 65536 + 255) / 256, 256>>>(W1l, W1r, W2l, W2r, W3);
    split_x_kernel<<<(NN * D / 4 + 255) / 256, 256>>>(x);

    // ---- layer 1 ----
    aggregate_kernel<<<aggBlocks, 256>>>(x, ahi, alo);
    ovf_kernel<<<32, 256>>>(x);
    fixsplit_kernel<<<16, 256>>>(ahi, alo);
    mma_gemm<true, true, true, true><<<gemmGrid, 256, SMEMSZ>>>(
        ahi, alo, wthi + 0 * 65536, wtlo + 0 * 65536,
        xhi, xlo, wthi + 1 * 65536, wtlo + 1 * 65536,
        b1, h1, h1hi, h1lo);

    // ---- layer 2 ----
    aggregate_kernel<<<aggBlocks, 256>>>(h1, ahi, alo);
    ovf_kernel<<<32, 256>>>(h1);
    fixsplit_kernel<<<16, 256>>>(ahi, alo);
    mma_gemm<true, true, false, true><<<gemmGrid, 256, SMEMSZ>>>(
        ahi, alo, wthi + 2 * 65536, wtlo + 2 * 65536,
        h1hi, h1lo, wthi + 3 * 65536, wtlo + 3 * 65536,
        b2, nullptr, h2hi, h2lo);

    // ---- head ----
    mma_gemm<false, false, true, false><<<gemmGrid, 256, SMEMSZ>>>(
        h2hi, h2lo, wthi + 4 * 65536, wtlo + 4 * 65536,
        nullptr, nullptr, nullptr, nullptr,
        b3, out, nullptr, nullptr);
}

// round 7
// speedup vs baseline: 1.9343x; 1.0351x over previous
#include <cuda_runtime.h>
#include <cuda_bf16.h>
#include <cstdint>

#define NN 100000
#define D  256
#define NE 1600000
#define CAP 128
#define MAXOVF 65536

typedef __nv_bfloat16 bf16;

// ---------------- scratch (device globals: allocations are forbidden) -------
__device__ float g_agg[(size_t)NN * D];       // fp32 agg (overflow path only)
__device__ bf16  g_xhi[(size_t)NN * D];
__device__ bf16  g_xlo[(size_t)NN * D];
__device__ bf16  g_ahi[(size_t)NN * D];
__device__ bf16  g_alo[(size_t)NN * D];
__device__ bf16  g_h1hi[(size_t)NN * D];
__device__ bf16  g_h1lo[(size_t)NN * D];
__device__ bf16  g_h2hi[(size_t)NN * D];
__device__ bf16  g_h2lo[(size_t)NN * D];
__device__ bf16  g_wthi[5 * 65536];           // transposed weights [N][K], split
__device__ bf16  g_wtlo[5 * 65536];
__device__ int   g_cnt[NN];
__device__ int   g_srclist[(size_t)NN * CAP];
__device__ int   g_ovf[2 * MAXOVF];
__device__ int   g_novf;
__device__ int   g_is64;

// ---------------- helpers ----------------------------------------------------
__device__ __forceinline__ uint32_t smem_u32(const void* p) {
    uint32_t a;
    asm("{ .reg .u64 t; cvta.to.shared.u64 t, %1; cvt.u32.u64 %0, t; }"
        : "=r"(a) : "l"(p));
    return a;
}
__device__ __forceinline__ void cp16(uint32_t dst, const void* src, int sz) {
    asm volatile("cp.async.cg.shared.global [%0], [%1], 16, %2;"
                 :: "r"(dst), "l"(src), "r"(sz) : "memory");
}
__device__ __forceinline__ void cp_commit() {
    asm volatile("cp.async.commit_group;" ::: "memory");
}
template<int N>
__device__ __forceinline__ void cp_wait() {
    asm volatile("cp.async.wait_group %0;" :: "n"(N) : "memory");
}
__device__ __forceinline__ void ldsm4(uint32_t* r, uint32_t addr) {
    asm volatile("ldmatrix.sync.aligned.m8n8.x4.shared.b16 {%0,%1,%2,%3}, [%4];"
                 : "=r"(r[0]), "=r"(r[1]), "=r"(r[2]), "=r"(r[3]) : "r"(addr));
}
__device__ __forceinline__ void mma16816(float* c, const uint32_t* a, const uint32_t* b) {
    asm volatile("mma.sync.aligned.m16n8k16.row.col.f32.bf16.bf16.f32 "
                 "{%0,%1,%2,%3}, {%4,%5,%6,%7}, {%8,%9}, {%0,%1,%2,%3};"
                 : "+f"(c[0]), "+f"(c[1]), "+f"(c[2]), "+f"(c[3])
                 : "r"(a[0]), "r"(a[1]), "r"(a[2]), "r"(a[3]),
                   "r"(b[0]), "r"(b[1]));
}
__device__ __forceinline__ uint32_t pack_bf2(float a, float b) {
    __nv_bfloat162 t = __floats2bfloat162_rn(a, b);
    return *reinterpret_cast<uint32_t*>(&t);
}
__device__ __forceinline__ float2 bf2_to_f2(uint32_t u) {
    __nv_bfloat162 b = *reinterpret_cast<__nv_bfloat162*>(&u);
    return __bfloat1622float2(b);
}
__device__ __forceinline__ void split1(float v, float& hi, float& lo) {
    bf16 h = __float2bfloat16(v);
    hi = __bfloat162float(h);
    lo = v - hi;
}

// ---------------- small utility kernels --------------------------------------
__global__ void zero_int_kernel(int* __restrict__ p, int n) {
    int i = blockIdx.x * blockDim.x + threadIdx.x;
    if (i < n) p[i] = 0;
}
__global__ void probe_kernel(const int* __restrict__ w) {
    if (threadIdx.x == 0) {
        int all_zero = 1;
        for (int i = 1; i < 128; i += 2)
            if (w[i] != 0) { all_zero = 0; break; }
        g_is64 = all_zero;
        g_novf = 0;
    }
}
__global__ void build_kernel(const int* __restrict__ w) {
    int e = blockIdx.x * blockDim.x + threadIdx.x;
    if (e >= NE) return;
    int s, d;
    if (g_is64) { s = w[2 * e]; d = w[2 * (NE + e)]; }
    else        { s = w[e];     d = w[NE + e];       }
    int pos = atomicAdd(&g_cnt[d], 1);
    if (pos < CAP) {
        g_srclist[(size_t)d * CAP + pos] = s;
    } else {
        int o = atomicAdd(&g_novf, 1);
        if (o < MAXOVF) { g_ovf[2 * o] = s; g_ovf[2 * o + 1] = d; }
    }
}
// transpose + split the 5 weight matrices: WT[m][n*256+k] = W_m[k*256+n]
__global__ void prep_weights(const float* __restrict__ W1l, const float* __restrict__ W1r,
                             const float* __restrict__ W2l, const float* __restrict__ W2r,
                             const float* __restrict__ W3) {
    int i = blockIdx.x * blockDim.x + threadIdx.x;
    if (i >= 5 * 65536) return;
    int m = i >> 16, idx = i & 65535;
    int n = idx >> 8, k = idx & 255;
    const float* W = (m == 0) ? W1l : (m == 1) ? W1r : (m == 2) ? W2l
                   : (m == 3) ? W2r : W3;
    float v = W[k * 256 + n], hi, lo;
    split1(v, hi, lo);
    g_wthi[i] = __float2bfloat16(hi);
    g_wtlo[i] = __float2bfloat16(lo);
}
__global__ void split_x_kernel(const float* __restrict__ x) {
    size_t i = (size_t)(blockIdx.x * blockDim.x + threadIdx.x) * 4;
    if (i >= (size_t)NN * D) return;
    float4 v = *(const float4*)(x + i);
    float h0, l0, h1, l1, h2, l2, h3, l3;
    split1(v.x, h0, l0); split1(v.y, h1, l1);
    split1(v.z, h2, l2); split1(v.w, h3, l3);
    *(uint2*)((bf16*)g_xhi + i) = make_uint2(pack_bf2(h0, h1), pack_bf2(h2, h3));
    *(uint2*)((bf16*)g_xlo + i) = make_uint2(pack_bf2(l0, l1), pack_bf2(l2, l3));
}

// ---------------- gather aggregation -----------------------------------------
// SPLITIN=false: read fp32 feat rows. SPLITIN=true: reconstruct from hi+lo bf16.
template<bool SPLITIN>
__global__ __launch_bounds__(256)
void aggregate_kernel(const float* __restrict__ feat,
                      const bf16* __restrict__ fhi, const bf16* __restrict__ flo,
                      bf16* __restrict__ outhi, bf16* __restrict__ outlo) {
    int warp = (blockIdx.x * blockDim.x + threadIdx.x) >> 5;
    int lane = threadIdx.x & 31;
    if (warp >= NN) return;
    int deg = g_cnt[warp];
    const int* lst = g_srclist + (size_t)warp * CAP;

    float4 a0 = make_float4(0.f, 0.f, 0.f, 0.f);
    float4 a1 = make_float4(0.f, 0.f, 0.f, 0.f);
    int nIn = min(deg, CAP);
    for (int base = 0; base < nIn; base += 32) {
        int sv = 0;
        if (base + lane < nIn) sv = lst[base + lane];
        int cnt = min(nIn - base, 32);
#pragma unroll 4
        for (int j = 0; j < cnt; j++) {
            int sj = __shfl_sync(0xffffffffu, sv, j);
            float4 v0, v1;
            if (SPLITIN) {
                const uint2* hr = (const uint2*)(fhi + (size_t)sj * D);
                const uint2* lr = (const uint2*)(flo + (size_t)sj * D);
                uint2 h0 = hr[lane], h1v = hr[lane + 32];
                uint2 l0 = lr[lane], l1v = lr[lane + 32];
                float2 p, q;
                p = bf2_to_f2(h0.x); q = bf2_to_f2(l0.x); v0.x = p.x + q.x; v0.y = p.y + q.y;
                p = bf2_to_f2(h0.y); q = bf2_to_f2(l0.y); v0.z = p.x + q.x; v0.w = p.y + q.y;
                p = bf2_to_f2(h1v.x); q = bf2_to_f2(l1v.x); v1.x = p.x + q.x; v1.y = p.y + q.y;
                p = bf2_to_f2(h1v.y); q = bf2_to_f2(l1v.y); v1.z = p.x + q.x; v1.w = p.y + q.y;
            } else {
                const float4* xs = (const float4*)(feat + (size_t)sj * D);
                v0 = xs[lane];
                v1 = xs[lane + 32];
            }
            a0.x += v0.x; a0.y += v0.y; a0.z += v0.z; a0.w += v0.w;
            a1.x += v1.x; a1.y += v1.y; a1.z += v1.z; a1.w += v1.w;
        }
    }
    float inv = 1.0f / fmaxf((float)deg, 1.0f);
    a0.x *= inv; a0.y *= inv; a0.z *= inv; a0.w *= inv;
    a1.x *= inv; a1.y *= inv; a1.z *= inv; a1.w *= inv;

    if (deg > CAP) {   // rare overflow path needs the fp32 partial mean
        float4* ad = (float4*)(g_agg + (size_t)warp * D);
        ad[lane]      = a0;
        ad[lane + 32] = a1;
    }

    float h, l, h2, l2, h3, l3, h4, l4;
    split1(a0.x, h, l); split1(a0.y, h2, l2); split1(a0.z, h3, l3); split1(a0.w, h4, l4);
    *(uint2*)(outhi + (size_t)warp * D + lane * 4) = make_uint2(pack_bf2(h, h2), pack_bf2(h3, h4));
    *(uint2*)(outlo + (size_t)warp * D + lane * 4) = make_uint2(pack_bf2(l, l2), pack_bf2(l3, l4));
    split1(a1.x, h, l); split1(a1.y, h2, l2); split1(a1.z, h3, l3); split1(a1.w, h4, l4);
    *(uint2*)(outhi + (size_t)warp * D + 128 + lane * 4) = make_uint2(pack_bf2(h, h2), pack_bf2(h3, h4));
    *(uint2*)(outlo + (size_t)warp * D + 128 + lane * 4) = make_uint2(pack_bf2(l, l2), pack_bf2(l3, l4));
}

// overflow fallback: add remaining edges into fp32 agg (reads feat or hi+lo)
template<bool SPLITIN>
__global__ void ovf_kernel(const float* __restrict__ feat,
                           const bf16* __restrict__ fhi, const bf16* __restrict__ flo) {
    int lane = threadIdx.x & 31;
    int w    = (blockIdx.x * blockDim.x + threadIdx.x) >> 5;
    int nw   = (gridDim.x * blockDim.x) >> 5;
    int n = min(g_novf, MAXOVF);
    for (int e = w; e < n; e += nw) {
        int s = g_ovf[2 * e], d = g_ovf[2 * e + 1];
        float inv = 1.0f / fmaxf((float)g_cnt[d], 1.0f);
        float* ad = g_agg + (size_t)d * D;
        for (int i = lane; i < D; i += 32) {
            float v;
            if (SPLITIN)
                v = __bfloat162float(fhi[(size_t)s * D + i]) +
                    __bfloat162float(flo[(size_t)s * D + i]);
            else
                v = feat[(size_t)s * D + i];
            atomicAdd(ad + i, v * inv);
        }
    }
}
__global__ void fixsplit_kernel(bf16* __restrict__ outhi, bf16* __restrict__ outlo) {
    int lane = threadIdx.x & 31;
    int w    = (blockIdx.x * blockDim.x + threadIdx.x) >> 5;
    int nw   = (gridDim.x * blockDim.x) >> 5;
    int n = min(g_novf, MAXOVF);
    for (int e = w; e < n; e += nw) {
        int d = g_ovf[2 * e + 1];
        const float* src = g_agg + (size_t)d * D;
        for (int c = lane; c < D; c += 32) {
            float hi, lo;
            split1(src[c], hi, lo);
            outhi[(size_t)d * D + c] = __float2bfloat16(hi);
            outlo[(size_t)d * D + c] = __float2bfloat16(lo);
        }
    }
}

// ---------------- mma.sync GEMM ----------------------------------------------
// CTA: 128 rows x 128 cols. 8 warps (4m x 2n), warp tile 32x64.
// C = [relu]( A1@W1' (+ A2@W2') + bias ); 3-term bf16 split per product.
// Smem stage: AH | AL | BH | BL, each 128 rows x 32 k bf16, row stride 80B.
#define ROWB   80
#define MAT_SZ 10240            // 128 * 80
#define STAGE  (4 * MAT_SZ)     // 40960
#define SMEMSZ (2 * STAGE)      // 81920

template<bool DUAL, bool RELU, bool F32OUT, bool SPLITOUT>
__global__ __launch_bounds__(256, 2)
void mma_gemm(const bf16* __restrict__ a1hi, const bf16* __restrict__ a1lo,
              const bf16* __restrict__ w1hi, const bf16* __restrict__ w1lo,
              const bf16* __restrict__ a2hi, const bf16* __restrict__ a2lo,
              const bf16* __restrict__ w2hi, const bf16* __restrict__ w2lo,
              const float* __restrict__ bias,
              float* __restrict__ Cf,
              bf16* __restrict__ Chi, bf16* __restrict__ Clo) {
    extern __shared__ char smem[];
    const uint32_t sb = smem_u32(smem);
    const int tid  = threadIdx.x;
    const int wid  = tid >> 5;
    const int lane = tid & 31;
    const int wm   = wid & 3;        // m strip: wm*32
    const int wn   = wid >> 2;       // n strip: wn*64
    const int m0   = blockIdx.x * 128;
    const int n0   = blockIdx.y * 128;

    float acc[2][8][4];
#pragma unroll
    for (int mi = 0; mi < 2; mi++)
#pragma unroll
        for (int ni = 0; ni < 8; ni++)
#pragma unroll
            for (int q = 0; q < 4; q++) acc[mi][ni][q] = 0.f;

    const int nIter = (DUAL ? 2 : 1) * 8;    // K chunks of 32

    auto prefetch = [&](int buf, int it) {
        const int rep   = it >> 3;
        const int kbase = (it & 7) * 32;
        const bf16* Ah = rep ? a2hi : a1hi;
        const bf16* Al = rep ? a2lo : a1lo;
        const bf16* Wh = rep ? w2hi : w1hi;
        const bf16* Wl = rep ? w2lo : w1lo;
        const uint32_t bb = sb + buf * STAGE;
#pragma unroll
        for (int i = 0; i < 2; i++) {
            int q   = tid + i * 256;         // 0..511
            int row = q >> 2, c4 = q & 3;
            uint32_t dsto = (uint32_t)(row * ROWB + c4 * 16);
            int grow = m0 + row;
            int arow = grow < NN ? grow : 0;
            int sz   = grow < NN ? 16 : 0;
            cp16(bb + 0 * MAT_SZ + dsto, Ah + (size_t)arow * D + kbase + c4 * 8, sz);
            cp16(bb + 1 * MAT_SZ + dsto, Al + (size_t)arow * D + kbase + c4 * 8, sz);
            cp16(bb + 2 * MAT_SZ + dsto, Wh + (size_t)(n0 + row) * D + kbase + c4 * 8, 16);
            cp16(bb + 3 * MAT_SZ + dsto, Wl + (size_t)(n0 + row) * D + kbase + c4 * 8, 16);
        }
    };

    prefetch(0, 0);
    cp_commit();

    const int alr = lane & 15, akh = lane >> 4;                        // A lane map
    const int bnr = lane & 7, bkh = (lane >> 3) & 1, btl = lane >> 4;  // B lane map

    for (int it = 0; it < nIter; it++) {
        if (it + 1 < nIter) { prefetch((it + 1) & 1, it + 1); cp_commit(); cp_wait<1>(); }
        else                { cp_wait<0>(); }
        __syncthreads();

        const uint32_t bb = sb + (it & 1) * STAGE;
        const uint32_t AHb = bb, ALb = bb + MAT_SZ, BHb = bb + 2 * MAT_SZ, BLb = bb + 3 * MAT_SZ;

#pragma unroll
        for (int k16 = 0; k16 < 2; k16++) {
            const uint32_t a_off = (uint32_t)((wm * 32 + alr) * ROWB + (k16 * 16 + akh * 8) * 2);
            const uint32_t b_off = (uint32_t)((wn * 64 + btl * 8 + bnr) * ROWB + (k16 * 16 + bkh * 8) * 2);

            uint32_t ah[2][4], al[2][4];
            ldsm4(ah[0], AHb + a_off);
            ldsm4(ah[1], AHb + a_off + 16 * ROWB);
            ldsm4(al[0], ALb + a_off);
            ldsm4(al[1], ALb + a_off + 16 * ROWB);

            // Process B in ni-pairs: only one 4-reg B fragment live at a time.
#pragma unroll
            for (int nh = 0; nh < 4; nh++) {
                uint32_t r[4];
                ldsm4(r, BHb + b_off + nh * 16 * ROWB);
#pragma unroll
                for (int mi = 0; mi < 2; mi++) {
                    mma16816(acc[mi][2 * nh],     ah[mi], r);
                    mma16816(acc[mi][2 * nh + 1], ah[mi], r + 2);
                    mma16816(acc[mi][2 * nh],     al[mi], r);
                    mma16816(acc[mi][2 * nh + 1], al[mi], r + 2);
                }
                ldsm4(r, BLb + b_off + nh * 16 * ROWB);
#pragma unroll
                for (int mi = 0; mi < 2; mi++) {
                    mma16816(acc[mi][2 * nh],     ah[mi], r);
                    mma16816(acc[mi][2 * nh + 1], ah[mi], r + 2);
                }
            }
        }
        __syncthreads();
    }

    // -------- epilogue --------
    const int rbase = m0 + wm * 32 + (lane >> 2);
    const int cbase = n0 + wn * 64 + (lane & 3) * 2;
#pragma unroll
    for (int ni = 0; ni < 8; ni++) {
        const int col = cbase + ni * 8;
        const float b0 = bias[col], b1 = bias[col + 1];
#pragma unroll
        for (int mi = 0; mi < 2; mi++) {
#pragma unroll
            for (int rr = 0; rr < 2; rr++) {
                int row = rbase + mi * 16 + rr * 8;
                if (row >= NN) continue;
                float v0 = acc[mi][ni][rr * 2 + 0] + b0;
                float v1 = acc[mi][ni][rr * 2 + 1] + b1;
                if (RELU) { v0 = fmaxf(v0, 0.f); v1 = fmaxf(v1, 0.f); }
                if (F32OUT)
                    *(float2*)(Cf + (size_t)row * D + col) = make_float2(v0, v1);
                if (SPLITOUT) {
                    float h0, l0, h1, l1;
                    split1(v0, h0, l0); split1(v1, h1, l1);
                    *(uint32_t*)(Chi + (size_t)row * D + col) = pack_bf2(h0, h1);
                    *(uint32_t*)(Clo + (size_t)row * D + col) = pack_bf2(l0, l1);
                }
            }
        }
    }
}

// ---------------- launch ------------------------------------------------------
extern "C" void kernel_launch(void* const* d_in, const int* in_sizes, int n_in,
                              void* d_out, int out_size) {
    const float* x   = (const float*)d_in[0];
    const int*   ei  = (const int*)d_in[1];
    const float* W1l = (const float*)d_in[2];
    const float* b1  = (const float*)d_in[3];
    const float* W1r = (const float*)d_in[4];
    const float* W2l = (const float*)d_in[5];
    const float* b2  = (const float*)d_in[6];
    const float* W2r = (const float*)d_in[7];
    const float* W3  = (const float*)d_in[8];
    const float* b3  = (const float*)d_in[9];
    float* out = (float*)d_out;

    int* cnt;
    bf16 *xhi, *xlo, *ahi, *alo, *h1hi, *h1lo, *h2hi, *h2lo, *wthi, *wtlo;
    cudaGetSymbolAddress((void**)&cnt,  g_cnt);
    cudaGetSymbolAddress((void**)&xhi,  g_xhi);
    cudaGetSymbolAddress((void**)&xlo,  g_xlo);
    cudaGetSymbolAddress((void**)&ahi,  g_ahi);
    cudaGetSymbolAddress((void**)&alo,  g_alo);
    cudaGetSymbolAddress((void**)&h1hi, g_h1hi);
    cudaGetSymbolAddress((void**)&h1lo, g_h1lo);
    cudaGetSymbolAddress((void**)&h2hi, g_h2hi);
    cudaGetSymbolAddress((void**)&h2lo, g_h2lo);
    cudaGetSymbolAddress((void**)&wthi, g_wthi);
    cudaGetSymbolAddress((void**)&wtlo, g_wtlo);

    cudaFuncSetAttribute(mma_gemm<true,  true,  false, true>,
                         cudaFuncAttributeMaxDynamicSharedMemorySize, SMEMSZ);
    cudaFuncSetAttribute(mma_gemm<false, false, true,  false>,
                         cudaFuncAttributeMaxDynamicSharedMemorySize, SMEMSZ);

    dim3 gemmGrid((NN + 127) / 128, 2);            // (782, 2)
    const int aggBlocks = (NN * 32 + 255) / 256;

    // ---- graph prep ----
    probe_kernel<<<1, 32>>>(ei);
    zero_int_kernel<<<(NN + 255) / 256, 256>>>(cnt, NN);
    build_kernel<<<(NE + 255) / 256, 256>>>(ei);
    prep_weights<<<(5 * 65536 + 255) / 256, 256>>>(W1l, W1r, W2l, W2r, W3);
    split_x_kernel<<<(NN * D / 4 + 255) / 256, 256>>>(x);

    // ---- layer 1 ----
    aggregate_kernel<false><<<aggBlocks, 256>>>(x, nullptr, nullptr, ahi, alo);
    ovf_kernel<false><<<32, 256>>>(x, nullptr, nullptr);
    fixsplit_kernel<<<16, 256>>>(ahi, alo);
    mma_gemm<true, true, false, true><<<gemmGrid, 256, SMEMSZ>>>(
        ahi, alo, wthi + 0 * 65536, wtlo + 0 * 65536,
        xhi, xlo, wthi + 1 * 65536, wtlo + 1 * 65536,
        b1, nullptr, h1hi, h1lo);

    // ---- layer 2 ----
    aggregate_kernel<true><<<aggBlocks, 256>>>(nullptr, h1hi, h1lo, ahi, alo);
    ovf_kernel<true><<<32, 256>>>(nullptr, h1hi, h1lo);
    fixsplit_kernel<<<16, 256>>>(ahi, alo);
    mma_gemm<true, true, false, true><<<gemmGrid, 256, SMEMSZ>>>(
        ahi, alo, wthi + 2 * 65536, wtlo + 2 * 65536,
        h1hi, h1lo, wthi + 3 * 65536, wtlo + 3 * 65536,
        b2, nullptr, h2hi, h2lo);

    // ---- head ----
    mma_gemm<false, false, true, false><<<gemmGrid, 256, SMEMSZ>>>(
        h2hi, h2lo, wthi + 4 * 65536, wtlo + 4 * 65536,
        nullptr, nullptr, nullptr, nullptr,
        b3, out, nullptr, nullptr);
}

// round 8
// speedup vs baseline: 2.1559x; 1.1146x over previous
#include <cuda_runtime.h>
#include <cuda_fp16.h>
#include <cstdint>

#define NN 100000
#define D  256
#define NE 1600000
#define CAP 128
#define MAXOVF 65536

typedef __half fp16;

// ---------------- scratch (device globals: allocations are forbidden) -------
__device__ float g_agg[(size_t)NN * D];       // fp32 agg (overflow path only)
__device__ fp16  g_xh [(size_t)NN * D];
__device__ fp16  g_xl [(size_t)NN * D];
__device__ fp16  g_ah [(size_t)NN * D];
__device__ fp16  g_al [(size_t)NN * D];
__device__ fp16  g_h1h[(size_t)NN * D];
__device__ fp16  g_h1l[(size_t)NN * D];
__device__ fp16  g_h2h[(size_t)NN * D];
__device__ fp16  g_h2l[(size_t)NN * D];
__device__ fp16  g_wtf[5 * 65536];            // transposed weights [N][K], fp16
__device__ int   g_cnt[NN];
__device__ int   g_srclist[(size_t)NN * CAP];
__device__ int   g_ovf[2 * MAXOVF];
__device__ int   g_novf;
__device__ int   g_is64;

// ---------------- helpers ----------------------------------------------------
__device__ __forceinline__ uint32_t smem_u32(const void* p) {
    uint32_t a;
    asm("{ .reg .u64 t; cvta.to.shared.u64 t, %1; cvt.u32.u64 %0, t; }"
        : "=r"(a) : "l"(p));
    return a;
}
__device__ __forceinline__ void cp16(uint32_t dst, const void* src, int sz) {
    asm volatile("cp.async.cg.shared.global [%0], [%1], 16, %2;"
                 :: "r"(dst), "l"(src), "r"(sz) : "memory");
}
__device__ __forceinline__ void cp_commit() {
    asm volatile("cp.async.commit_group;" ::: "memory");
}
template<int N>
__device__ __forceinline__ void cp_wait() {
    asm volatile("cp.async.wait_group %0;" :: "n"(N) : "memory");
}
__device__ __forceinline__ void ldsm4(uint32_t* r, uint32_t addr) {
    asm volatile("ldmatrix.sync.aligned.m8n8.x4.shared.b16 {%0,%1,%2,%3}, [%4];"
                 : "=r"(r[0]), "=r"(r[1]), "=r"(r[2]), "=r"(r[3]) : "r"(addr));
}
__device__ __forceinline__ void mma16816(float* c, const uint32_t* a, const uint32_t* b) {
    asm volatile("mma.sync.aligned.m16n8k16.row.col.f32.f16.f16.f32 "
                 "{%0,%1,%2,%3}, {%4,%5,%6,%7}, {%8,%9}, {%0,%1,%2,%3};"
                 : "+f"(c[0]), "+f"(c[1]), "+f"(c[2]), "+f"(c[3])
                 : "r"(a[0]), "r"(a[1]), "r"(a[2]), "r"(a[3]),
                   "r"(b[0]), "r"(b[1]));
}
__device__ __forceinline__ uint32_t pack_h2(float a, float b) {
    __half2 t = __floats2half2_rn(a, b);
    return *reinterpret_cast<uint32_t*>(&t);
}
__device__ __forceinline__ float2 h2_to_f2(uint32_t u) {
    __half2 h = *reinterpret_cast<__half2*>(&u);
    return __half22float2(h);
}
__device__ __forceinline__ void split1(float v, float& hi, float& lo) {
    fp16 h = __float2half_rn(v);
    hi = __half2float(h);
    lo = v - hi;
}

// ---------------- small utility kernels --------------------------------------
__global__ void zero_int_kernel(int* __restrict__ p, int n) {
    int i = blockIdx.x * blockDim.x + threadIdx.x;
    if (i < n) p[i] = 0;
}
__global__ void probe_kernel(const int* __restrict__ w) {
    if (threadIdx.x == 0) {
        int all_zero = 1;
        for (int i = 1; i < 128; i += 2)
            if (w[i] != 0) { all_zero = 0; break; }
        g_is64 = all_zero;
        g_novf = 0;
    }
}
__global__ void build_kernel(const int* __restrict__ w) {
    int e = blockIdx.x * blockDim.x + threadIdx.x;
    if (e >= NE) return;
    int s, d;
    if (g_is64) { s = w[2 * e]; d = w[2 * (NE + e)]; }
    else        { s = w[e];     d = w[NE + e];       }
    int pos = atomicAdd(&g_cnt[d], 1);
    if (pos < CAP) {
        g_srclist[(size_t)d * CAP + pos] = s;
    } else {
        int o = atomicAdd(&g_novf, 1);
        if (o < MAXOVF) { g_ovf[2 * o] = s; g_ovf[2 * o + 1] = d; }
    }
}
// transpose the 5 weight matrices to [N][K], single fp16
__global__ void prep_weights(const float* __restrict__ W1l, const float* __restrict__ W1r,
                             const float* __restrict__ W2l, const float* __restrict__ W2r,
                             const float* __restrict__ W3) {
    int i = blockIdx.x * blockDim.x + threadIdx.x;
    if (i >= 5 * 65536) return;
    int m = i >> 16, idx = i & 65535;
    int n = idx >> 8, k = idx & 255;
    const float* W = (m == 0) ? W1l : (m == 1) ? W1r : (m == 2) ? W2l
                   : (m == 3) ? W2r : W3;
    g_wtf[i] = __float2half_rn(W[k * 256 + n]);
}
__global__ void split_x_kernel(const float* __restrict__ x) {
    size_t i = (size_t)(blockIdx.x * blockDim.x + threadIdx.x) * 4;
    if (i >= (size_t)NN * D) return;
    float4 v = *(const float4*)(x + i);
    float h0, l0, h1, l1, h2, l2, h3, l3;
    split1(v.x, h0, l0); split1(v.y, h1, l1);
    split1(v.z, h2, l2); split1(v.w, h3, l3);
    *(uint2*)((fp16*)g_xh + i) = make_uint2(pack_h2(h0, h1), pack_h2(h2, h3));
    *(uint2*)((fp16*)g_xl + i) = make_uint2(pack_h2(l0, l1), pack_h2(l2, l3));
}

// ---------------- gather aggregation -----------------------------------------
// SPLITIN=false: read fp32 feat rows. SPLITIN=true: reconstruct from hi+lo fp16.
template<bool SPLITIN>
__global__ __launch_bounds__(256)
void aggregate_kernel(const float* __restrict__ feat,
                      const fp16* __restrict__ fh, const fp16* __restrict__ fl,
                      fp16* __restrict__ outh, fp16* __restrict__ outl) {
    int warp = (blockIdx.x * blockDim.x + threadIdx.x) >> 5;
    int lane = threadIdx.x & 31;
    if (warp >= NN) return;
    int deg = g_cnt[warp];
    const int* lst = g_srclist + (size_t)warp * CAP;

    float4 a0 = make_float4(0.f, 0.f, 0.f, 0.f);
    float4 a1 = make_float4(0.f, 0.f, 0.f, 0.f);
    int nIn = min(deg, CAP);
    for (int base = 0; base < nIn; base += 32) {
        int sv = 0;
        if (base + lane < nIn) sv = lst[base + lane];
        int cnt = min(nIn - base, 32);
#pragma unroll 4
        for (int j = 0; j < cnt; j++) {
            int sj = __shfl_sync(0xffffffffu, sv, j);
            float4 v0, v1;
            if (SPLITIN) {
                const uint2* hr = (const uint2*)(fh + (size_t)sj * D);
                const uint2* lr = (const uint2*)(fl + (size_t)sj * D);
                uint2 hu0 = hr[lane], hu1 = hr[lane + 32];
                uint2 lu0 = lr[lane], lu1 = lr[lane + 32];
                float2 p, q;
                p = h2_to_f2(hu0.x); q = h2_to_f2(lu0.x); v0.x = p.x + q.x; v0.y = p.y + q.y;
                p = h2_to_f2(hu0.y); q = h2_to_f2(lu0.y); v0.z = p.x + q.x; v0.w = p.y + q.y;
                p = h2_to_f2(hu1.x); q = h2_to_f2(lu1.x); v1.x = p.x + q.x; v1.y = p.y + q.y;
                p = h2_to_f2(hu1.y); q = h2_to_f2(lu1.y); v1.z = p.x + q.x; v1.w = p.y + q.y;
            } else {
                const float4* xs = (const float4*)(feat + (size_t)sj * D);
                v0 = xs[lane];
                v1 = xs[lane + 32];
            }
            a0.x += v0.x; a0.y += v0.y; a0.z += v0.z; a0.w += v0.w;
            a1.x += v1.x; a1.y += v1.y; a1.z += v1.z; a1.w += v1.w;
        }
    }
    float inv = 1.0f / fmaxf((float)deg, 1.0f);
    a0.x *= inv; a0.y *= inv; a0.z *= inv; a0.w *= inv;
    a1.x *= inv; a1.y *= inv; a1.z *= inv; a1.w *= inv;

    if (deg > CAP) {   // rare overflow path needs the fp32 partial mean
        float4* ad = (float4*)(g_agg + (size_t)warp * D);
        ad[lane]      = a0;
        ad[lane + 32] = a1;
    }

    float h, l, h2, l2, h3, l3, h4, l4;
    split1(a0.x, h, l); split1(a0.y, h2, l2); split1(a0.z, h3, l3); split1(a0.w, h4, l4);
    *(uint2*)(outh + (size_t)warp * D + lane * 4) = make_uint2(pack_h2(h, h2), pack_h2(h3, h4));
    *(uint2*)(outl + (size_t)warp * D + lane * 4) = make_uint2(pack_h2(l, l2), pack_h2(l3, l4));
    split1(a1.x, h, l); split1(a1.y, h2, l2); split1(a1.z, h3, l3); split1(a1.w, h4, l4);
    *(uint2*)(outh + (size_t)warp * D + 128 + lane * 4) = make_uint2(pack_h2(h, h2), pack_h2(h3, h4));
    *(uint2*)(outl + (size_t)warp * D + 128 + lane * 4) = make_uint2(pack_h2(l, l2), pack_h2(l3, l4));
}

// overflow fallback: add remaining edges into fp32 agg (reads feat or hi+lo)
template<bool SPLITIN>
__global__ void ovf_kernel(const float* __restrict__ feat,
                           const fp16* __restrict__ fh, const fp16* __restrict__ fl) {
    int lane = threadIdx.x & 31;
    int w    = (blockIdx.x * blockDim.x + threadIdx.x) >> 5;
    int nw   = (gridDim.x * blockDim.x) >> 5;
    int n = min(g_novf, MAXOVF);
    for (int e = w; e < n; e += nw) {
        int s = g_ovf[2 * e], d = g_ovf[2 * e + 1];
        float inv = 1.0f / fmaxf((float)g_cnt[d], 1.0f);
        float* ad = g_agg + (size_t)d * D;
        for (int i = lane; i < D; i += 32) {
            float v;
            if (SPLITIN)
                v = __half2float(fh[(size_t)s * D + i]) +
                    __half2float(fl[(size_t)s * D + i]);
            else
                v = feat[(size_t)s * D + i];
            atomicAdd(ad + i, v * inv);
        }
    }
}
__global__ void fixsplit_kernel(fp16* __restrict__ outh, fp16* __restrict__ outl) {
    int lane = threadIdx.x & 31;
    int w    = (blockIdx.x * blockDim.x + threadIdx.x) >> 5;
    int nw   = (gridDim.x * blockDim.x) >> 5;
    int n = min(g_novf, MAXOVF);
    for (int e = w; e < n; e += nw) {
        int d = g_ovf[2 * e + 1];
        const float* src = g_agg + (size_t)d * D;
        for (int c = lane; c < D; c += 32) {
            float hi, lo;
            split1(src[c], hi, lo);
            outh[(size_t)d * D + c] = __float2half_rn(hi);
            outl[(size_t)d * D + c] = __float2half_rn(lo);
        }
    }
}

// ---------------- mma.sync GEMM ----------------------------------------------
// CTA: 128 rows x 256 cols (all outputs). 8 warps (4m x 2n), warp tile 32x128.
// C = [relu]( A1@W1' (+ A2@W2') + bias )
// A split into fp16 hi+lo (2 MMA terms); W single fp16.
// Smem stage: AH | AL (128x32 fp16, row 80B) | B (256x32 fp16, row 80B).
#define ROWB   80
#define MAT_A  10240            // 128 * 80
#define MAT_B  20480            // 256 * 80
#define STAGE  (2 * MAT_A + MAT_B)   // 40960
#define SMEMSZ (2 * STAGE)           // 81920

template<bool DUAL, bool RELU, bool F32OUT, bool SPLITOUT>
__global__ __launch_bounds__(256)
void mma_gemm(const fp16* __restrict__ a1h, const fp16* __restrict__ a1l,
              const fp16* __restrict__ w1,
              const fp16* __restrict__ a2h, const fp16* __restrict__ a2l,
              const fp16* __restrict__ w2,
              const float* __restrict__ bias,
              float* __restrict__ Cf,
              fp16* __restrict__ Ch, fp16* __restrict__ Cl) {
    extern __shared__ char smem[];
    const uint32_t sb = smem_u32(smem);
    const int tid  = threadIdx.x;
    const int wid  = tid >> 5;
    const int lane = tid & 31;
    const int wm   = wid & 3;        // m strip: wm*32
    const int wn   = wid >> 2;       // n strip: wn*128
    const int m0   = blockIdx.x * 128;

    float acc[2][16][4];
#pragma unroll
    for (int mi = 0; mi < 2; mi++)
#pragma unroll
        for (int ni = 0; ni < 16; ni++)
#pragma unroll
            for (int q = 0; q < 4; q++) acc[mi][ni][q] = 0.f;

    const int nIter = (DUAL ? 2 : 1) * 8;    // K chunks of 32

    auto prefetch = [&](int buf, int it) {
        const int rep   = it >> 3;
        const int kbase = (it & 7) * 32;
        const fp16* Ah = rep ? a2h : a1h;
        const fp16* Al = rep ? a2l : a1l;
        const fp16* W  = rep ? w2  : w1;
        const uint32_t bb = sb + buf * STAGE;
        // A: 128 rows x 4 quads = 512 slots, for AH and AL
#pragma unroll
        for (int i = 0; i < 2; i++) {
            int q   = tid + i * 256;
            int row = q >> 2, c4 = q & 3;
            uint32_t dsto = (uint32_t)(row * ROWB + c4 * 16);
            int grow = m0 + row;
            int arow = grow < NN ? grow : 0;
            int sz   = grow < NN ? 16 : 0;
            cp16(bb + 0 * MAT_A + dsto, Ah + (size_t)arow * D + kbase + c4 * 8, sz);
            cp16(bb + 1 * MAT_A + dsto, Al + (size_t)arow * D + kbase + c4 * 8, sz);
        }
        // B: 256 rows x 4 quads = 1024 slots
#pragma unroll
        for (int i = 0; i < 4; i++) {
            int q   = tid + i * 256;
            int row = q >> 2, c4 = q & 3;
            uint32_t dsto = (uint32_t)(row * ROWB + c4 * 16);
            cp16(bb + 2 * MAT_A + dsto, W + (size_t)row * D + kbase + c4 * 8, 16);
        }
    };

    prefetch(0, 0);
    cp_commit();

    const int alr = lane & 15, akh = lane >> 4;                        // A lane map
    const int bnr = lane & 7, bkh = (lane >> 3) & 1, btl = lane >> 4;  // B lane map

    for (int it = 0; it < nIter; it++) {
        if (it + 1 < nIter) { prefetch((it + 1) & 1, it + 1); cp_commit(); cp_wait<1>(); }
        else                { cp_wait<0>(); }
        __syncthreads();

        const uint32_t bb = sb + (it & 1) * STAGE;
        const uint32_t AHb = bb, ALb = bb + MAT_A, Bb = bb + 2 * MAT_A;

#pragma unroll
        for (int k16 = 0; k16 < 2; k16++) {
            const uint32_t a_off = (uint32_t)((wm * 32 + alr) * ROWB + (k16 * 16 + akh * 8) * 2);
            const uint32_t b_off = (uint32_t)((wn * 128 + btl * 8 + bnr) * ROWB + (k16 * 16 + bkh * 8) * 2);

            uint32_t ah[2][4], al[2][4];
            ldsm4(ah[0], AHb + a_off);
            ldsm4(ah[1], AHb + a_off + 16 * ROWB);
            ldsm4(al[0], ALb + a_off);
            ldsm4(al[1], ALb + a_off + 16 * ROWB);

#pragma unroll
            for (int nh = 0; nh < 8; nh++) {
                uint32_t r[4];
                ldsm4(r, Bb + b_off + nh * 16 * ROWB);
#pragma unroll
                for (int mi = 0; mi < 2; mi++) {
                    mma16816(acc[mi][2 * nh],     ah[mi], r);
                    mma16816(acc[mi][2 * nh + 1], ah[mi], r + 2);
                    mma16816(acc[mi][2 * nh],     al[mi], r);
                    mma16816(acc[mi][2 * nh + 1], al[mi], r + 2);
                }
            }
        }
        __syncthreads();
    }

    // -------- epilogue --------
    const int rbase = m0 + wm * 32 + (lane >> 2);
    const int cbase = wn * 128 + (lane & 3) * 2;
#pragma unroll
    for (int ni = 0; ni < 16; ni++) {
        const int col = cbase + ni * 8;
        const float b0 = bias[col], b1 = bias[col + 1];
#pragma unroll
        for (int mi = 0; mi < 2; mi++) {
#pragma unroll
            for (int rr = 0; rr < 2; rr++) {
                int row = rbase + mi * 16 + rr * 8;
                if (row >= NN) continue;
                float v0 = acc[mi][ni][rr * 2 + 0] + b0;
                float v1 = acc[mi][ni][rr * 2 + 1] + b1;
                if (RELU) { v0 = fmaxf(v0, 0.f); v1 = fmaxf(v1, 0.f); }
                if (F32OUT)
                    *(float2*)(Cf + (size_t)row * D + col) = make_float2(v0, v1);
                if (SPLITOUT) {
                    float h0, l0, h1, l1;
                    split1(v0, h0, l0); split1(v1, h1, l1);
                    *(uint32_t*)(Ch + (size_t)row * D + col) = pack_h2(h0, h1);
                    *(uint32_t*)(Cl + (size_t)row * D + col) = pack_h2(l0, l1);
                }
            }
        }
    }
}

// ---------------- launch ------------------------------------------------------
extern "C" void kernel_launch(void* const* d_in, const int* in_sizes, int n_in,
                              void* d_out, int out_size) {
    const float* x   = (const float*)d_in[0];
    const int*   ei  = (const int*)d_in[1];
    const float* W1l = (const float*)d_in[2];
    const float* b1  = (const float*)d_in[3];
    const float* W1r = (const float*)d_in[4];
    const float* W2l = (const float*)d_in[5];
    const float* b2  = (const float*)d_in[6];
    const float* W2r = (const float*)d_in[7];
    const float* W3  = (const float*)d_in[8];
    const float* b3  = (const float*)d_in[9];
    float* out = (float*)d_out;

    int* cnt;
    fp16 *xh, *xl, *ah, *al, *h1h, *h1l, *h2h, *h2l, *wtf;
    cudaGetSymbolAddress((void**)&cnt, g_cnt);
    cudaGetSymbolAddress((void**)&xh,  g_xh);
    cudaGetSymbolAddress((void**)&xl,  g_xl);
    cudaGetSymbolAddress((void**)&ah,  g_ah);
    cudaGetSymbolAddress((void**)&al,  g_al);
    cudaGetSymbolAddress((void**)&h1h, g_h1h);
    cudaGetSymbolAddress((void**)&h1l, g_h1l);
    cudaGetSymbolAddress((void**)&h2h, g_h2h);
    cudaGetSymbolAddress((void**)&h2l, g_h2l);
    cudaGetSymbolAddress((void**)&wtf, g_wtf);

    cudaFuncSetAttribute(mma_gemm<true,  true,  false, true>,
                         cudaFuncAttributeMaxDynamicSharedMemorySize, SMEMSZ);
    cudaFuncSetAttribute(mma_gemm<false, false, true,  false>,
                         cudaFuncAttributeMaxDynamicSharedMemorySize, SMEMSZ);

    const int gemmBlocks = (NN + 127) / 128;       // 782
    const int aggBlocks  = (NN * 32 + 255) / 256;

    // ---- graph prep ----
    probe_kernel<<<1, 32>>>(ei);
    zero_int_kernel<<<(NN + 255) / 256, 256>>>(cnt, NN);
    build_kernel<<<(NE + 255) / 256, 256>>>(ei);
    prep_weights<<<(5 * 65536 + 255) / 256, 256>>>(W1l, W1r, W2l, W2r, W3);
    split_x_kernel<<<(NN * D / 4 + 255) / 256, 256>>>(x);

    // ---- layer 1 ----
    aggregate_kernel<false><<<aggBlocks, 256>>>(x, nullptr, nullptr, ah, al);
    ovf_kernel<false><<<32, 256>>>(x, nullptr, nullptr);
    fixsplit_kernel<<<16, 256>>>(ah, al);
    mma_gemm<true, true, false, true><<<gemmBlocks, 256, SMEMSZ>>>(
        ah, al, wtf + 0 * 65536,
        xh, xl, wtf + 1 * 65536,
        b1, nullptr, h1h, h1l);

    // ---- layer 2 ----
    aggregate_kernel<true><<<aggBlocks, 256>>>(nullptr, h1h, h1l, ah, al);
    ovf_kernel<true><<<32, 256>>>(nullptr, h1h, h1l);
    fixsplit_kernel<<<16, 256>>>(ah, al);
    mma_gemm<true, true, false, true><<<gemmBlocks, 256, SMEMSZ>>>(
        ah, al, wtf + 2 * 65536,
        h1h, h1l, wtf + 3 * 65536,
        b2, nullptr, h2h, h2l);

    // ---- head ----
    mma_gemm<false, false, true, false><<<gemmBlocks, 256, SMEMSZ>>>(
        h2h, h2l, wtf + 4 * 65536,
        nullptr, nullptr, nullptr,
        b3, out, nullptr, nullptr);
}

// round 9
// speedup vs baseline: 2.5636x; 1.1891x over previous
#include <cuda_runtime.h>
#include <cuda_fp16.h>
#include <cstdint>

#define NN 100000
#define D  256
#define NE 1600000
#define CAP 128
#define MAXOVF 65536

typedef __half fp16;

// ---------------- scratch (device globals: allocations are forbidden) -------
__device__ float g_agg[(size_t)NN * D];       // fp32 agg (overflow path only)
__device__ fp16  g_xh [(size_t)NN * D];
__device__ fp16  g_xl [(size_t)NN * D];
__device__ fp16  g_ah [(size_t)NN * D];
__device__ fp16  g_al [(size_t)NN * D];
__device__ fp16  g_h1h[(size_t)NN * D];
__device__ fp16  g_h1l[(size_t)NN * D];
__device__ fp16  g_h2h[(size_t)NN * D];
__device__ fp16  g_h2l[(size_t)NN * D];
__device__ fp16  g_wtf[5 * 65536];            // transposed weights [N][K], fp16
__device__ int   g_cnt[NN];
__device__ int   g_srclist[(size_t)NN * CAP];
__device__ int   g_ovf[2 * MAXOVF];
__device__ int   g_novf;
__device__ int   g_is64;

// ---------------- helpers ----------------------------------------------------
__device__ __forceinline__ uint32_t smem_u32(const void* p) {
    uint32_t a;
    asm("{ .reg .u64 t; cvta.to.shared.u64 t, %1; cvt.u32.u64 %0, t; }"
        : "=r"(a) : "l"(p));
    return a;
}
__device__ __forceinline__ void cp16(uint32_t dst, const void* src, int sz) {
    asm volatile("cp.async.cg.shared.global [%0], [%1], 16, %2;"
                 :: "r"(dst), "l"(src), "r"(sz) : "memory");
}
__device__ __forceinline__ void cp_commit() {
    asm volatile("cp.async.commit_group;" ::: "memory");
}
template<int N>
__device__ __forceinline__ void cp_wait() {
    asm volatile("cp.async.wait_group %0;" :: "n"(N) : "memory");
}
__device__ __forceinline__ void ldsm4(uint32_t* r, uint32_t addr) {
    asm volatile("ldmatrix.sync.aligned.m8n8.x4.shared.b16 {%0,%1,%2,%3}, [%4];"
                 : "=r"(r[0]), "=r"(r[1]), "=r"(r[2]), "=r"(r[3]) : "r"(addr));
}
__device__ __forceinline__ void mma16816(float* c, const uint32_t* a, const uint32_t* b) {
    asm volatile("mma.sync.aligned.m16n8k16.row.col.f32.f16.f16.f32 "
                 "{%0,%1,%2,%3}, {%4,%5,%6,%7}, {%8,%9}, {%0,%1,%2,%3};"
                 : "+f"(c[0]), "+f"(c[1]), "+f"(c[2]), "+f"(c[3])
                 : "r"(a[0]), "r"(a[1]), "r"(a[2]), "r"(a[3]),
                   "r"(b[0]), "r"(b[1]));
}
__device__ __forceinline__ uint32_t pack_h2(float a, float b) {
    __half2 t = __floats2half2_rn(a, b);
    return *reinterpret_cast<uint32_t*>(&t);
}
__device__ __forceinline__ float2 h2_to_f2(uint32_t u) {
    __half2 h = *reinterpret_cast<__half2*>(&u);
    return __half22float2(h);
}
__device__ __forceinline__ void split1(float v, float& hi, float& lo) {
    fp16 h = __float2half_rn(v);
    hi = __half2float(h);
    lo = v - hi;
}

// ---------------- small utility kernels --------------------------------------
__global__ void zero_int_kernel(int* __restrict__ p, int n) {
    int i = blockIdx.x * blockDim.x + threadIdx.x;
    if (i < n) p[i] = 0;
}
__global__ void probe_kernel(const int* __restrict__ w) {
    if (threadIdx.x == 0) {
        int all_zero = 1;
        for (int i = 1; i < 128; i += 2)
            if (w[i] != 0) { all_zero = 0; break; }
        g_is64 = all_zero;
        g_novf = 0;
    }
}
__global__ void build_kernel(const int* __restrict__ w) {
    int e = blockIdx.x * blockDim.x + threadIdx.x;
    if (e >= NE) return;
    int s, d;
    if (g_is64) { s = w[2 * e]; d = w[2 * (NE + e)]; }
    else        { s = w[e];     d = w[NE + e];       }
    int pos = atomicAdd(&g_cnt[d], 1);
    if (pos < CAP) {
        g_srclist[(size_t)d * CAP + pos] = s;
    } else {
        int o = atomicAdd(&g_novf, 1);
        if (o < MAXOVF) { g_ovf[2 * o] = s; g_ovf[2 * o + 1] = d; }
    }
}
// transpose the 5 weight matrices to [N][K], single fp16
__global__ void prep_weights(const float* __restrict__ W1l, const float* __restrict__ W1r,
                             const float* __restrict__ W2l, const float* __restrict__ W2r,
                             const float* __restrict__ W3) {
    int i = blockIdx.x * blockDim.x + threadIdx.x;
    if (i >= 5 * 65536) return;
    int m = i >> 16, idx = i & 65535;
    int n = idx >> 8, k = idx & 255;
    const float* W = (m == 0) ? W1l : (m == 1) ? W1r : (m == 2) ? W2l
                   : (m == 3) ? W2r : W3;
    g_wtf[i] = __float2half_rn(W[k * 256 + n]);
}
__global__ void split_x_kernel(const float* __restrict__ x) {
    size_t i = (size_t)(blockIdx.x * blockDim.x + threadIdx.x) * 4;
    if (i >= (size_t)NN * D) return;
    float4 v = *(const float4*)(x + i);
    float h0, l0, h1, l1, h2, l2, h3, l3;
    split1(v.x, h0, l0); split1(v.y, h1, l1);
    split1(v.z, h2, l2); split1(v.w, h3, l3);
    *(uint2*)((fp16*)g_xh + i) = make_uint2(pack_h2(h0, h1), pack_h2(h2, h3));
    *(uint2*)((fp16*)g_xl + i) = make_uint2(pack_h2(l0, l1), pack_h2(l2, l3));
}

// ---------------- gather aggregation -----------------------------------------
// Reads fp16 hi-features only (512B/row); accumulates fp32; one uint4 per lane.
__global__ __launch_bounds__(256)
void aggregate_kernel(const fp16* __restrict__ fh,
                      fp16* __restrict__ outh, fp16* __restrict__ outl) {
    int warp = (blockIdx.x * blockDim.x + threadIdx.x) >> 5;
    int lane = threadIdx.x & 31;
    if (warp >= NN) return;
    int deg = g_cnt[warp];
    const int* lst = g_srclist + (size_t)warp * CAP;

    float a[8];
#pragma unroll
    for (int q = 0; q < 8; q++) a[q] = 0.f;

    int nIn = min(deg, CAP);
    for (int base = 0; base < nIn; base += 32) {
        int sv = 0;
        if (base + lane < nIn) sv = lst[base + lane];
        int cnt = min(nIn - base, 32);
#pragma unroll 4
        for (int j = 0; j < cnt; j++) {
            int sj = __shfl_sync(0xffffffffu, sv, j);
            uint4 v = ((const uint4*)(fh + (size_t)sj * D))[lane];
            float2 p;
            p = h2_to_f2(v.x); a[0] += p.x; a[1] += p.y;
            p = h2_to_f2(v.y); a[2] += p.x; a[3] += p.y;
            p = h2_to_f2(v.z); a[4] += p.x; a[5] += p.y;
            p = h2_to_f2(v.w); a[6] += p.x; a[7] += p.y;
        }
    }
    float inv = 1.0f / fmaxf((float)deg, 1.0f);
#pragma unroll
    for (int q = 0; q < 8; q++) a[q] *= inv;

    if (deg > CAP) {   // rare overflow path needs the fp32 partial mean
        float* ad = g_agg + (size_t)warp * D + lane * 8;
        *(float4*)ad       = make_float4(a[0], a[1], a[2], a[3]);
        *(float4*)(ad + 4) = make_float4(a[4], a[5], a[6], a[7]);
    }

    float h[8], l[8];
#pragma unroll
    for (int q = 0; q < 8; q++) split1(a[q], h[q], l[q]);
    uint4 hv = make_uint4(pack_h2(h[0], h[1]), pack_h2(h[2], h[3]),
                          pack_h2(h[4], h[5]), pack_h2(h[6], h[7]));
    uint4 lv = make_uint4(pack_h2(l[0], l[1]), pack_h2(l[2], l[3]),
                          pack_h2(l[4], l[5]), pack_h2(l[6], l[7]));
    *(uint4*)(outh + (size_t)warp * D + lane * 8) = hv;
    *(uint4*)(outl + (size_t)warp * D + lane * 8) = lv;
}

// overflow fallback: add remaining edges into fp32 agg (reads fp16 hi feats)
__global__ void ovf_kernel(const fp16* __restrict__ fh) {
    int lane = threadIdx.x & 31;
    int w    = (blockIdx.x * blockDim.x + threadIdx.x) >> 5;
    int nw   = (gridDim.x * blockDim.x) >> 5;
    int n = min(g_novf, MAXOVF);
    for (int e = w; e < n; e += nw) {
        int s = g_ovf[2 * e], d = g_ovf[2 * e + 1];
        float inv = 1.0f / fmaxf((float)g_cnt[d], 1.0f);
        float* ad = g_agg + (size_t)d * D;
        for (int i = lane; i < D; i += 32)
            atomicAdd(ad + i, __half2float(fh[(size_t)s * D + i]) * inv);
    }
}
__global__ void fixsplit_kernel(fp16* __restrict__ outh, fp16* __restrict__ outl) {
    int lane = threadIdx.x & 31;
    int w    = (blockIdx.x * blockDim.x + threadIdx.x) >> 5;
    int nw   = (gridDim.x * blockDim.x) >> 5;
    int n = min(g_novf, MAXOVF);
    for (int e = w; e < n; e += nw) {
        int d = g_ovf[2 * e + 1];
        const float* src = g_agg + (size_t)d * D;
        for (int c = lane; c < D; c += 32) {
            float hi, lo;
            split1(src[c], hi, lo);
            outh[(size_t)d * D + c] = __float2half_rn(hi);
            outl[(size_t)d * D + c] = __float2half_rn(lo);
        }
    }
}

// ---------------- mma.sync GEMM ----------------------------------------------
// CTA: 128 rows x 256 cols (all outputs). 8 warps (4m x 2n), warp tile 32x128.
// C = [relu]( A1@W1' (+ A2@W2') + bias )
// A split into fp16 hi+lo (2 MMA terms); W single fp16.
// Smem stage: AH | AL (128x32 fp16, row 80B) | B (256x32 fp16, row 80B).
#define ROWB   80
#define MAT_A  10240            // 128 * 80
#define MAT_B  20480            // 256 * 80
#define STAGE  (2 * MAT_A + MAT_B)   // 40960
#define SMEMSZ (2 * STAGE)           // 81920

template<bool DUAL, bool RELU, bool F32OUT, bool SPLITOUT>
__global__ __launch_bounds__(256)
void mma_gemm(const fp16* __restrict__ a1h, const fp16* __restrict__ a1l,
              const fp16* __restrict__ w1,
              const fp16* __restrict__ a2h, const fp16* __restrict__ a2l,
              const fp16* __restrict__ w2,
              const float* __restrict__ bias,
              float* __restrict__ Cf,
              fp16* __restrict__ Ch, fp16* __restrict__ Cl) {
    extern __shared__ char smem[];
    const uint32_t sb = smem_u32(smem);
    const int tid  = threadIdx.x;
    const int wid  = tid >> 5;
    const int lane = tid & 31;
    const int wm   = wid & 3;        // m strip: wm*32
    const int wn   = wid >> 2;       // n strip: wn*128
    const int m0   = blockIdx.x * 128;

    float acc[2][16][4];
#pragma unroll
    for (int mi = 0; mi < 2; mi++)
#pragma unroll
        for (int ni = 0; ni < 16; ni++)
#pragma unroll
            for (int q = 0; q < 4; q++) acc[mi][ni][q] = 0.f;

    const int nIter = (DUAL ? 2 : 1) * 8;    // K chunks of 32

    auto prefetch = [&](int buf, int it) {
        const int rep   = it >> 3;
        const int kbase = (it & 7) * 32;
        const fp16* Ah = rep ? a2h : a1h;
        const fp16* Al = rep ? a2l : a1l;
        const fp16* W  = rep ? w2  : w1;
        const uint32_t bb = sb + buf * STAGE;
#pragma unroll
        for (int i = 0; i < 2; i++) {
            int q   = tid + i * 256;
            int row = q >> 2, c4 = q & 3;
            uint32_t dsto = (uint32_t)(row * ROWB + c4 * 16);
            int grow = m0 + row;
            int arow = grow < NN ? grow : 0;
            int sz   = grow < NN ? 16 : 0;
            cp16(bb + 0 * MAT_A + dsto, Ah + (size_t)arow * D + kbase + c4 * 8, sz);
            cp16(bb + 1 * MAT_A + dsto, Al + (size_t)arow * D + kbase + c4 * 8, sz);
        }
#pragma unroll
        for (int i = 0; i < 4; i++) {
            int q   = tid + i * 256;
            int row = q >> 2, c4 = q & 3;
            uint32_t dsto = (uint32_t)(row * ROWB + c4 * 16);
            cp16(bb + 2 * MAT_A + dsto, W + (size_t)row * D + kbase + c4 * 8, 16);
        }
    };

    prefetch(0, 0);
    cp_commit();

    const int alr = lane & 15, akh = lane >> 4;                        // A lane map
    const int bnr = lane & 7, bkh = (lane >> 3) & 1, btl = lane >> 4;  // B lane map

    for (int it = 0; it < nIter; it++) {
        if (it + 1 < nIter) { prefetch((it + 1) & 1, it + 1); cp_commit(); cp_wait<1>(); }
        else                { cp_wait<0>(); }
        __syncthreads();

        const uint32_t bb = sb + (it & 1) * STAGE;
        const uint32_t AHb = bb, ALb = bb + MAT_A, Bb = bb + 2 * MAT_A;

#pragma unroll
        for (int k16 = 0; k16 < 2; k16++) {
            const uint32_t a_off = (uint32_t)((wm * 32 + alr) * ROWB + (k16 * 16 + akh * 8) * 2);
            const uint32_t b_off = (uint32_t)((wn * 128 + btl * 8 + bnr) * ROWB + (k16 * 16 + bkh * 8) * 2);

            uint32_t ah[2][4], al[2][4];
            ldsm4(ah[0], AHb + a_off);
            ldsm4(ah[1], AHb + a_off + 16 * ROWB);
            ldsm4(al[0], ALb + a_off);
            ldsm4(al[1], ALb + a_off + 16 * ROWB);

#pragma unroll
            for (int nh = 0; nh < 8; nh++) {
                uint32_t r[4];
                ldsm4(r, Bb + b_off + nh * 16 * ROWB);
#pragma unroll
                for (int mi = 0; mi < 2; mi++) {
                    mma16816(acc[mi][2 * nh],     ah[mi], r);
                    mma16816(acc[mi][2 * nh + 1], ah[mi], r + 2);
                    mma16816(acc[mi][2 * nh],     al[mi], r);
                    mma16816(acc[mi][2 * nh + 1], al[mi], r + 2);
                }
            }
        }
        __syncthreads();
    }

    // -------- epilogue --------
    const int rbase = m0 + wm * 32 + (lane >> 2);
    const int cbase = wn * 128 + (lane & 3) * 2;
#pragma unroll
    for (int ni = 0; ni < 16; ni++) {
        const int col = cbase + ni * 8;
        const float b0 = bias[col], b1 = bias[col + 1];
#pragma unroll
        for (int mi = 0; mi < 2; mi++) {
#pragma unroll
            for (int rr = 0; rr < 2; rr++) {
                int row = rbase + mi * 16 + rr * 8;
                if (row >= NN) continue;
                float v0 = acc[mi][ni][rr * 2 + 0] + b0;
                float v1 = acc[mi][ni][rr * 2 + 1] + b1;
                if (RELU) { v0 = fmaxf(v0, 0.f); v1 = fmaxf(v1, 0.f); }
                if (F32OUT)
                    *(float2*)(Cf + (size_t)row * D + col) = make_float2(v0, v1);
                if (SPLITOUT) {
                    float h0, l0, h1, l1;
                    split1(v0, h0, l0); split1(v1, h1, l1);
                    *(uint32_t*)(Ch + (size_t)row * D + col) = pack_h2(h0, h1);
                    *(uint32_t*)(Cl + (size_t)row * D + col) = pack_h2(l0, l1);
                }
            }
        }
    }
}

// ---------------- launch ------------------------------------------------------
extern "C" void kernel_launch(void* const* d_in, const int* in_sizes, int n_in,
                              void* d_out, int out_size) {
    const float* x   = (const float*)d_in[0];
    const int*   ei  = (const int*)d_in[1];
    const float* W1l = (const float*)d_in[2];
    const float* b1  = (const float*)d_in[3];
    const float* W1r = (const float*)d_in[4];
    const float* W2l = (const float*)d_in[5];
    const float* b2  = (const float*)d_in[6];
    const float* W2r = (const float*)d_in[7];
    const float* W3  = (const float*)d_in[8];
    const float* b3  = (const float*)d_in[9];
    float* out = (float*)d_out;

    int* cnt;
    fp16 *xh, *xl, *ah, *al, *h1h, *h1l, *h2h, *h2l, *wtf;
    cudaGetSymbolAddress((void**)&cnt, g_cnt);
    cudaGetSymbolAddress((void**)&xh,  g_xh);
    cudaGetSymbolAddress((void**)&xl,  g_xl);
    cudaGetSymbolAddress((void**)&ah,  g_ah);
    cudaGetSymbolAddress((void**)&al,  g_al);
    cudaGetSymbolAddress((void**)&h1h, g_h1h);
    cudaGetSymbolAddress((void**)&h1l, g_h1l);
    cudaGetSymbolAddress((void**)&h2h, g_h2h);
    cudaGetSymbolAddress((void**)&h2l, g_h2l);
    cudaGetSymbolAddress((void**)&wtf, g_wtf);

    cudaFuncSetAttribute(mma_gemm<true,  true,  false, true>,
                         cudaFuncAttributeMaxDynamicSharedMemorySize, SMEMSZ);
    cudaFuncSetAttribute(mma_gemm<false, false, true,  false>,
                         cudaFuncAttributeMaxDynamicSharedMemorySize, SMEMSZ);

    const int gemmBlocks = (NN + 127) / 128;       // 782
    const int aggBlocks  = (NN * 32 + 255) / 256;

    // ---- graph prep ----
    probe_kernel<<<1, 32>>>(ei);
    zero_int_kernel<<<(NN + 255) / 256, 256>>>(cnt, NN);
    build_kernel<<<(NE + 255) / 256, 256>>>(ei);
    prep_weights<<<(5 * 65536 + 255) / 256, 256>>>(W1l, W1r, W2l, W2r, W3);
    split_x_kernel<<<(NN * D / 4 + 255) / 256, 256>>>(x);

    // ---- layer 1 ----
    aggregate_kernel<<<aggBlocks, 256>>>(xh, ah, al);
    ovf_kernel<<<32, 256>>>(xh);
    fixsplit_kernel<<<16, 256>>>(ah, al);
    mma_gemm<true, true, false, true><<<gemmBlocks, 256, SMEMSZ>>>(
        ah, al, wtf + 0 * 65536,
        xh, xl, wtf + 1 * 65536,
        b1, nullptr, h1h, h1l);

    // ---- layer 2 ----
    aggregate_kernel<<<aggBlocks, 256>>>(h1h, ah, al);
    ovf_kernel<<<32, 256>>>(h1h);
    fixsplit_kernel<<<16, 256>>>(ah, al);
    mma_gemm<true, true, false, true><<<gemmBlocks, 256, SMEMSZ>>>(
        ah, al, wtf + 2 * 65536,
        h1h, h1l, wtf + 3 * 65536,
        b2, nullptr, h2h, h2l);

    // ---- head ----
    mma_gemm<false, false, true, false><<<gemmBlocks, 256, SMEMSZ>>>(
        h2h, h2l, wtf + 4 * 65536,
        nullptr, nullptr, nullptr,
        b3, out, nullptr, nullptr);
}

// round 10
// speedup vs baseline: 2.8754x; 1.1216x over previous
#include <cuda_runtime.h>
#include <cuda_fp16.h>
#include <cstdint>

#define NN 100000
#define D  256
#define NE 1600000
#define CAP 128
#define MAXOVF 65536

typedef __half fp16;

// ---------------- scratch (device globals: allocations are forbidden) -------
__device__ float g_agg[(size_t)NN * D];       // fp32 agg (overflow path only)
__device__ fp16  g_xh [(size_t)NN * D];
__device__ fp16  g_xl [(size_t)NN * D];
__device__ fp16  g_ah [(size_t)NN * D];
__device__ fp16  g_al [(size_t)NN * D];
__device__ fp16  g_h1h[(size_t)NN * D];
__device__ fp16  g_h1l[(size_t)NN * D];
__device__ fp16  g_h2h[(size_t)NN * D];
__device__ fp16  g_h2l[(size_t)NN * D];
__device__ fp16  g_wtf[5 * 65536];            // transposed weights [N][K], fp16
__device__ int   g_cnt[NN];
__device__ int   g_srclist[(size_t)NN * CAP];
__device__ int   g_ovf[2 * MAXOVF];
__device__ int   g_novf;
__device__ int   g_is64;

// ---------------- helpers ----------------------------------------------------
__device__ __forceinline__ uint32_t smem_u32(const void* p) {
    uint32_t a;
    asm("{ .reg .u64 t; cvta.to.shared.u64 t, %1; cvt.u32.u64 %0, t; }"
        : "=r"(a) : "l"(p));
    return a;
}
__device__ __forceinline__ void cp16(uint32_t dst, const void* src, int sz) {
    asm volatile("cp.async.cg.shared.global [%0], [%1], 16, %2;"
                 :: "r"(dst), "l"(src), "r"(sz) : "memory");
}
__device__ __forceinline__ void cp_commit() {
    asm volatile("cp.async.commit_group;" ::: "memory");
}
template<int N>
__device__ __forceinline__ void cp_wait() {
    asm volatile("cp.async.wait_group %0;" :: "n"(N) : "memory");
}
__device__ __forceinline__ void ldsm4(uint32_t* r, uint32_t addr) {
    asm volatile("ldmatrix.sync.aligned.m8n8.x4.shared.b16 {%0,%1,%2,%3}, [%4];"
                 : "=r"(r[0]), "=r"(r[1]), "=r"(r[2]), "=r"(r[3]) : "r"(addr));
}
__device__ __forceinline__ void mma16816(float* c, const uint32_t* a, const uint32_t* b) {
    asm volatile("mma.sync.aligned.m16n8k16.row.col.f32.f16.f16.f32 "
                 "{%0,%1,%2,%3}, {%4,%5,%6,%7}, {%8,%9}, {%0,%1,%2,%3};"
                 : "+f"(c[0]), "+f"(c[1]), "+f"(c[2]), "+f"(c[3])
                 : "r"(a[0]), "r"(a[1]), "r"(a[2]), "r"(a[3]),
                   "r"(b[0]), "r"(b[1]));
}
__device__ __forceinline__ uint32_t pack_h2(float a, float b) {
    __half2 t = __floats2half2_rn(a, b);
    return *reinterpret_cast<uint32_t*>(&t);
}
__device__ __forceinline__ float2 h2_to_f2(uint32_t u) {
    __half2 h = *reinterpret_cast<__half2*>(&u);
    return __half22float2(h);
}
__device__ __forceinline__ void split1(float v, float& hi, float& lo) {
    fp16 h = __float2half_rn(v);
    hi = __half2float(h);
    lo = v - hi;
}

// ---------------- small utility kernels --------------------------------------
__global__ void zero_int_kernel(int* __restrict__ p, int n) {
    int i = blockIdx.x * blockDim.x + threadIdx.x;
    if (i < n) p[i] = 0;
}
__global__ void probe_kernel(const int* __restrict__ w) {
    if (threadIdx.x == 0) {
        int all_zero = 1;
        for (int i = 1; i < 128; i += 2)
            if (w[i] != 0) { all_zero = 0; break; }
        g_is64 = all_zero;
        g_novf = 0;
    }
}
__global__ void build_kernel(const int* __restrict__ w) {
    int e = blockIdx.x * blockDim.x + threadIdx.x;
    if (e >= NE) return;
    int s, d;
    if (g_is64) { s = w[2 * e]; d = w[2 * (NE + e)]; }
    else        { s = w[e];     d = w[NE + e];       }
    int pos = atomicAdd(&g_cnt[d], 1);
    if (pos < CAP) {
        g_srclist[(size_t)d * CAP + pos] = s;
    } else {
        int o = atomicAdd(&g_novf, 1);
        if (o < MAXOVF) { g_ovf[2 * o] = s; g_ovf[2 * o + 1] = d; }
    }
}
// transpose the 5 weight matrices to [N][K], single fp16
__global__ void prep_weights(const float* __restrict__ W1l, const float* __restrict__ W1r,
                             const float* __restrict__ W2l, const float* __restrict__ W2r,
                             const float* __restrict__ W3) {
    int i = blockIdx.x * blockDim.x + threadIdx.x;
    if (i >= 5 * 65536) return;
    int m = i >> 16, idx = i & 65535;
    int n = idx >> 8, k = idx & 255;
    const float* W = (m == 0) ? W1l : (m == 1) ? W1r : (m == 2) ? W2l
                   : (m == 3) ? W2r : W3;
    g_wtf[i] = __float2half_rn(W[k * 256 + n]);
}
__global__ void split_x_kernel(const float* __restrict__ x) {
    size_t i = (size_t)(blockIdx.x * blockDim.x + threadIdx.x) * 4;
    if (i >= (size_t)NN * D) return;
    float4 v = *(const float4*)(x + i);
    float h0, l0, h1, l1, h2, l2, h3, l3;
    split1(v.x, h0, l0); split1(v.y, h1, l1);
    split1(v.z, h2, l2); split1(v.w, h3, l3);
    *(uint2*)((fp16*)g_xh + i) = make_uint2(pack_h2(h0, h1), pack_h2(h2, h3));
    *(uint2*)((fp16*)g_xl + i) = make_uint2(pack_h2(l0, l1), pack_h2(l2, l3));
}

// ---------------- gather aggregation -----------------------------------------
// Reads fp16 hi-features only (512B/row); accumulates fp32; one uint4 per lane.
__global__ __launch_bounds__(256)
void aggregate_kernel(const fp16* __restrict__ fh,
                      fp16* __restrict__ outh, fp16* __restrict__ outl) {
    int warp = (blockIdx.x * blockDim.x + threadIdx.x) >> 5;
    int lane = threadIdx.x & 31;
    if (warp >= NN) return;
    int deg = g_cnt[warp];
    const int* lst = g_srclist + (size_t)warp * CAP;

    float a[8];
#pragma unroll
    for (int q = 0; q < 8; q++) a[q] = 0.f;

    int nIn = min(deg, CAP);
    for (int base = 0; base < nIn; base += 32) {
        int sv = 0;
        if (base + lane < nIn) sv = lst[base + lane];
        int cnt = min(nIn - base, 32);
#pragma unroll 4
        for (int j = 0; j < cnt; j++) {
            int sj = __shfl_sync(0xffffffffu, sv, j);
            uint4 v = ((const uint4*)(fh + (size_t)sj * D))[lane];
            float2 p;
            p = h2_to_f2(v.x); a[0] += p.x; a[1] += p.y;
            p = h2_to_f2(v.y); a[2] += p.x; a[3] += p.y;
            p = h2_to_f2(v.z); a[4] += p.x; a[5] += p.y;
            p = h2_to_f2(v.w); a[6] += p.x; a[7] += p.y;
        }
    }
    float inv = 1.0f / fmaxf((float)deg, 1.0f);
#pragma unroll
    for (int q = 0; q < 8; q++) a[q] *= inv;

    if (deg > CAP) {   // rare overflow path needs the fp32 partial mean
        float* ad = g_agg + (size_t)warp * D + lane * 8;
        *(float4*)ad       = make_float4(a[0], a[1], a[2], a[3]);
        *(float4*)(ad + 4) = make_float4(a[4], a[5], a[6], a[7]);
    }

    float h[8], l[8];
#pragma unroll
    for (int q = 0; q < 8; q++) split1(a[q], h[q], l[q]);
    uint4 hv = make_uint4(pack_h2(h[0], h[1]), pack_h2(h[2], h[3]),
                          pack_h2(h[4], h[5]), pack_h2(h[6], h[7]));
    uint4 lv = make_uint4(pack_h2(l[0], l[1]), pack_h2(l[2], l[3]),
                          pack_h2(l[4], l[5]), pack_h2(l[6], l[7]));
    *(uint4*)(outh + (size_t)warp * D + lane * 8) = hv;
    *(uint4*)(outl + (size_t)warp * D + lane * 8) = lv;
}

// overflow fallback: add remaining edges into fp32 agg (reads fp16 hi feats)
__global__ void ovf_kernel(const fp16* __restrict__ fh) {
    int lane = threadIdx.x & 31;
    int w    = (blockIdx.x * blockDim.x + threadIdx.x) >> 5;
    int nw   = (gridDim.x * blockDim.x) >> 5;
    int n = min(g_novf, MAXOVF);
    for (int e = w; e < n; e += nw) {
        int s = g_ovf[2 * e], d = g_ovf[2 * e + 1];
        float inv = 1.0f / fmaxf((float)g_cnt[d], 1.0f);
        float* ad = g_agg + (size_t)d * D;
        for (int i = lane; i < D; i += 32)
            atomicAdd(ad + i, __half2float(fh[(size_t)s * D + i]) * inv);
    }
}
__global__ void fixsplit_kernel(fp16* __restrict__ outh, fp16* __restrict__ outl) {
    int lane = threadIdx.x & 31;
    int w    = (blockIdx.x * blockDim.x + threadIdx.x) >> 5;
    int nw   = (gridDim.x * blockDim.x) >> 5;
    int n = min(g_novf, MAXOVF);
    for (int e = w; e < n; e += nw) {
        int d = g_ovf[2 * e + 1];
        const float* src = g_agg + (size_t)d * D;
        for (int c = lane; c < D; c += 32) {
            float hi, lo;
            split1(src[c], hi, lo);
            outh[(size_t)d * D + c] = __float2half_rn(hi);
            outl[(size_t)d * D + c] = __float2half_rn(lo);
        }
    }
}

// ---------------- mma.sync GEMM ----------------------------------------------
// CTA: 128 rows x 128 cols, grid (782, 2), 2 CTAs/SM (4 warps/SMSP).
// 8 warps (4m x 2n), warp tile 32x64.
// C = [relu]( A1@W1' (+ A2@W2') + bias )
// A split into fp16 hi+lo (2 MMA terms); W single fp16.
// Smem stage: AH | AL (128x32 fp16, 80B rows) | B (128x32 fp16, 80B rows).
#define ROWB   80
#define MAT_A  10240            // 128 * 80
#define STAGE  (3 * MAT_A)      // 30720
#define SMEMSZ (2 * STAGE)      // 61440

template<bool DUAL, bool RELU, bool F32OUT, bool SPLITOUT>
__global__ __launch_bounds__(256, 2)
void mma_gemm(const fp16* __restrict__ a1h, const fp16* __restrict__ a1l,
              const fp16* __restrict__ w1,
              const fp16* __restrict__ a2h, const fp16* __restrict__ a2l,
              const fp16* __restrict__ w2,
              const float* __restrict__ bias,
              float* __restrict__ Cf,
              fp16* __restrict__ Ch, fp16* __restrict__ Cl) {
    extern __shared__ char smem[];
    const uint32_t sb = smem_u32(smem);
    const int tid  = threadIdx.x;
    const int wid  = tid >> 5;
    const int lane = tid & 31;
    const int wm   = wid & 3;        // m strip: wm*32
    const int wn   = wid >> 2;       // n strip: wn*64
    const int m0   = blockIdx.x * 128;
    const int n0   = blockIdx.y * 128;

    float acc[2][8][4];
#pragma unroll
    for (int mi = 0; mi < 2; mi++)
#pragma unroll
        for (int ni = 0; ni < 8; ni++)
#pragma unroll
            for (int q = 0; q < 4; q++) acc[mi][ni][q] = 0.f;

    const int nIter = (DUAL ? 2 : 1) * 8;    // K chunks of 32

    auto prefetch = [&](int buf, int it) {
        const int rep   = it >> 3;
        const int kbase = (it & 7) * 32;
        const fp16* Ah = rep ? a2h : a1h;
        const fp16* Al = rep ? a2l : a1l;
        const fp16* W  = rep ? w2  : w1;
        const uint32_t bb = sb + buf * STAGE;
        // A: 128 rows x 4 quads = 512 slots, AH and AL
#pragma unroll
        for (int i = 0; i < 2; i++) {
            int q   = tid + i * 256;
            int row = q >> 2, c4 = q & 3;
            uint32_t dsto = (uint32_t)(row * ROWB + c4 * 16);
            int grow = m0 + row;
            int arow = grow < NN ? grow : 0;
            int sz   = grow < NN ? 16 : 0;
            cp16(bb + 0 * MAT_A + dsto, Ah + (size_t)arow * D + kbase + c4 * 8, sz);
            cp16(bb + 1 * MAT_A + dsto, Al + (size_t)arow * D + kbase + c4 * 8, sz);
        }
        // B: this CTA's 128 weight rows x 4 quads = 512 slots
#pragma unroll
        for (int i = 0; i < 2; i++) {
            int q   = tid + i * 256;
            int row = q >> 2, c4 = q & 3;
            uint32_t dsto = (uint32_t)(row * ROWB + c4 * 16);
            cp16(bb + 2 * MAT_A + dsto, W + (size_t)(n0 + row) * D + kbase + c4 * 8, 16);
        }
    };

    prefetch(0, 0);
    cp_commit();

    const int alr = lane & 15, akh = lane >> 4;                        // A lane map
    const int bnr = lane & 7, bkh = (lane >> 3) & 1, btl = lane >> 4;  // B lane map

    for (int it = 0; it < nIter; it++) {
        if (it + 1 < nIter) { prefetch((it + 1) & 1, it + 1); cp_commit(); cp_wait<1>(); }
        else                { cp_wait<0>(); }
        __syncthreads();

        const uint32_t bb = sb + (it & 1) * STAGE;
        const uint32_t AHb = bb, ALb = bb + MAT_A, Bb = bb + 2 * MAT_A;

#pragma unroll
        for (int k16 = 0; k16 < 2; k16++) {
            const uint32_t a_off = (uint32_t)((wm * 32 + alr) * ROWB + (k16 * 16 + akh * 8) * 2);
            const uint32_t b_off = (uint32_t)((wn * 64 + btl * 8 + bnr) * ROWB + (k16 * 16 + bkh * 8) * 2);

            uint32_t ah[2][4], al[2][4];
            ldsm4(ah[0], AHb + a_off);
            ldsm4(ah[1], AHb + a_off + 16 * ROWB);
            ldsm4(al[0], ALb + a_off);
            ldsm4(al[1], ALb + a_off + 16 * ROWB);

            // B n16-fragments in pairs: both live -> RAW gap >= 4 on each acc.
#pragma unroll
            for (int np = 0; np < 2; np++) {
                uint32_t r0[4], r1[4];
                ldsm4(r0, Bb + b_off + (2 * np)     * 16 * ROWB);
                ldsm4(r1, Bb + b_off + (2 * np + 1) * 16 * ROWB);
#pragma unroll
                for (int mi = 0; mi < 2; mi++) {
                    mma16816(acc[mi][4 * np + 0], ah[mi], r0);
                    mma16816(acc[mi][4 * np + 1], ah[mi], r0 + 2);
                    mma16816(acc[mi][4 * np + 2], ah[mi], r1);
                    mma16816(acc[mi][4 * np + 3], ah[mi], r1 + 2);
                    mma16816(acc[mi][4 * np + 0], al[mi], r0);
                    mma16816(acc[mi][4 * np + 1], al[mi], r0 + 2);
                    mma16816(acc[mi][4 * np + 2], al[mi], r1);
                    mma16816(acc[mi][4 * np + 3], al[mi], r1 + 2);
                }
            }
        }
        __syncthreads();
    }

    // -------- epilogue --------
    const int rbase = m0 + wm * 32 + (lane >> 2);
    const int cbase = n0 + wn * 64 + (lane & 3) * 2;
#pragma unroll
    for (int ni = 0; ni < 8; ni++) {
        const int col = cbase + ni * 8;
        const float b0 = bias[col], b1 = bias[col + 1];
#pragma unroll
        for (int mi = 0; mi < 2; mi++) {
#pragma unroll
            for (int rr = 0; rr < 2; rr++) {
                int row = rbase + mi * 16 + rr * 8;
                if (row >= NN) continue;
                float v0 = acc[mi][ni][rr * 2 + 0] + b0;
                float v1 = acc[mi][ni][rr * 2 + 1] + b1;
                if (RELU) { v0 = fmaxf(v0, 0.f); v1 = fmaxf(v1, 0.f); }
                if (F32OUT)
                    *(float2*)(Cf + (size_t)row * D + col) = make_float2(v0, v1);
                if (SPLITOUT) {
                    float h0, l0, h1, l1;
                    split1(v0, h0, l0); split1(v1, h1, l1);
                    *(uint32_t*)(Ch + (size_t)row * D + col) = pack_h2(h0, h1);
                    *(uint32_t*)(Cl + (size_t)row * D + col) = pack_h2(l0, l1);
                }
            }
        }
    }
}

// ---------------- launch ------------------------------------------------------
extern "C" void kernel_launch(void* const* d_in, const int* in_sizes, int n_in,
                              void* d_out, int out_size) {
    const float* x   = (const float*)d_in[0];
    const int*   ei  = (const int*)d_in[1];
    const float* W1l = (const float*)d_in[2];
    const float* b1  = (const float*)d_in[3];
    const float* W1r = (const float*)d_in[4];
    const float* W2l = (const float*)d_in[5];
    const float* b2  = (const float*)d_in[6];
    const float* W2r = (const float*)d_in[7];
    const float* W3  = (const float*)d_in[8];
    const float* b3  = (const float*)d_in[9];
    float* out = (float*)d_out;

    int* cnt;
    fp16 *xh, *xl, *ah, *al, *h1h, *h1l, *h2h, *h2l, *wtf;
    cudaGetSymbolAddress((void**)&cnt, g_cnt);
    cudaGetSymbolAddress((void**)&xh,  g_xh);
    cudaGetSymbolAddress((void**)&xl,  g_xl);
    cudaGetSymbolAddress((void**)&ah,  g_ah);
    cudaGetSymbolAddress((void**)&al,  g_al);
    cudaGetSymbolAddress((void**)&h1h, g_h1h);
    cudaGetSymbolAddress((void**)&h1l, g_h1l);
    cudaGetSymbolAddress((void**)&h2h, g_h2h);
    cudaGetSymbolAddress((void**)&h2l, g_h2l);
    cudaGetSymbolAddress((void**)&wtf, g_wtf);

    cudaFuncSetAttribute(mma_gemm<true,  true,  false, true>,
                         cudaFuncAttributeMaxDynamicSharedMemorySize, SMEMSZ);
    cudaFuncSetAttribute(mma_gemm<false, false, true,  false>,
                         cudaFuncAttributeMaxDynamicSharedMemorySize, SMEMSZ);

    dim3 gemmGrid((NN + 127) / 128, 2);            // (782, 2)
    const int aggBlocks = (NN * 32 + 255) / 256;

    // ---- graph prep ----
    probe_kernel<<<1, 32>>>(ei);
    zero_int_kernel<<<(NN + 255) / 256, 256>>>(cnt, NN);
    build_kernel<<<(NE + 255) / 256, 256>>>(ei);
    prep_weights<<<(5 * 65536 + 255) / 256, 256>>>(W1l, W1r, W2l, W2r, W3);
    split_x_kernel<<<(NN * D / 4 + 255) / 256, 256>>>(x);

    // ---- layer 1 ----
    aggregate_kernel<<<aggBlocks, 256>>>(xh, ah, al);
    ovf_kernel<<<32, 256>>>(xh);
    fixsplit_kernel<<<16, 256>>>(ah, al);
    mma_gemm<true, true, false, true><<<gemmGrid, 256, SMEMSZ>>>(
        ah, al, wtf + 0 * 65536,
        xh, xl, wtf + 1 * 65536,
        b1, nullptr, h1h, h1l);

    // ---- layer 2 ----
    aggregate_kernel<<<aggBlocks, 256>>>(h1h, ah, al);
    ovf_kernel<<<32, 256>>>(h1h);
    fixsplit_kernel<<<16, 256>>>(ah, al);
    mma_gemm<true, true, false, true><<<gemmGrid, 256, SMEMSZ>>>(
        ah, al, wtf + 2 * 65536,
        h1h, h1l, wtf + 3 * 65536,
        b2, nullptr, h2h, h2l);

    // ---- head ----
    mma_gemm<false, false, true, false><<<gemmGrid, 256, SMEMSZ>>>(
        h2h, h2l, wtf + 4 * 65536,
        nullptr, nullptr, nullptr,
        b3, out, nullptr, nullptr);
}

// round 11
// speedup vs baseline: 4.3052x; 1.4973x over previous
#include <cuda_runtime.h>
#include <cuda_fp16.h>
#include <cstdint>

#define NN 100000
#define D  256
#define NE 1600000
#define CAP 128
#define MAXOVF 65536

typedef __half fp16;

// ---------------- scratch (device globals: allocations are forbidden) -------
__device__ float g_agg[(size_t)NN * D];       // fp32 agg (overflow path only)
__device__ fp16  g_xh [(size_t)NN * D];
__device__ fp16  g_ah [(size_t)NN * D];
__device__ fp16  g_h1h[(size_t)NN * D];
__device__ fp16  g_h2h[(size_t)NN * D];
__device__ fp16  g_wtf[5 * 65536];            // transposed weights [N][K], fp16
__device__ int   g_cnt[NN];
__device__ int   g_srclist[(size_t)NN * CAP];
__device__ int   g_ovf[2 * MAXOVF];
__device__ int   g_novf;
__device__ int   g_is64;

// ---------------- helpers ----------------------------------------------------
__device__ __forceinline__ uint32_t smem_u32(const void* p) {
    uint32_t a;
    asm("{ .reg .u64 t; cvta.to.shared.u64 t, %1; cvt.u32.u64 %0, t; }"
        : "=r"(a) : "l"(p));
    return a;
}
__device__ __forceinline__ void cp16(uint32_t dst, const void* src, int sz) {
    asm volatile("cp.async.cg.shared.global [%0], [%1], 16, %2;"
                 :: "r"(dst), "l"(src), "r"(sz) : "memory");
}
__device__ __forceinline__ void cp_commit() {
    asm volatile("cp.async.commit_group;" ::: "memory");
}
template<int N>
__device__ __forceinline__ void cp_wait() {
    asm volatile("cp.async.wait_group %0;" :: "n"(N) : "memory");
}
__device__ __forceinline__ void ldsm4(uint32_t* r, uint32_t addr) {
    asm volatile("ldmatrix.sync.aligned.m8n8.x4.shared.b16 {%0,%1,%2,%3}, [%4];"
                 : "=r"(r[0]), "=r"(r[1]), "=r"(r[2]), "=r"(r[3]) : "r"(addr));
}
__device__ __forceinline__ void mma16816(float* c, const uint32_t* a, const uint32_t* b) {
    asm volatile("mma.sync.aligned.m16n8k16.row.col.f32.f16.f16.f32 "
                 "{%0,%1,%2,%3}, {%4,%5,%6,%7}, {%8,%9}, {%0,%1,%2,%3};"
                 : "+f"(c[0]), "+f"(c[1]), "+f"(c[2]), "+f"(c[3])
                 : "r"(a[0]), "r"(a[1]), "r"(a[2]), "r"(a[3]),
                   "r"(b[0]), "r"(b[1]));
}
__device__ __forceinline__ uint32_t pack_h2(float a, float b) {
    __half2 t = __floats2half2_rn(a, b);
    return *reinterpret_cast<uint32_t*>(&t);
}
__device__ __forceinline__ float2 h2_to_f2(uint32_t u) {
    __half2 h = *reinterpret_cast<__half2*>(&u);
    return __half22float2(h);
}

// ---------------- small utility kernels --------------------------------------
__global__ void zero_int_kernel(int* __restrict__ p, int n) {
    int i = blockIdx.x * blockDim.x + threadIdx.x;
    if (i < n) p[i] = 0;
}
__global__ void probe_kernel(const int* __restrict__ w) {
    if (threadIdx.x == 0) {
        int all_zero = 1;
        for (int i = 1; i < 128; i += 2)
            if (w[i] != 0) { all_zero = 0; break; }
        g_is64 = all_zero;
        g_novf = 0;
    }
}
__global__ void build_kernel(const int* __restrict__ w) {
    int e = blockIdx.x * blockDim.x + threadIdx.x;
    if (e >= NE) return;
    int s, d;
    if (g_is64) { s = w[2 * e]; d = w[2 * (NE + e)]; }
    else        { s = w[e];     d = w[NE + e];       }
    int pos = atomicAdd(&g_cnt[d], 1);
    if (pos < CAP) {
        g_srclist[(size_t)d * CAP + pos] = s;
    } else {
        int o = atomicAdd(&g_novf, 1);
        if (o < MAXOVF) { g_ovf[2 * o] = s; g_ovf[2 * o + 1] = d; }
    }
}
// transpose the 5 weight matrices to [N][K], single fp16
__global__ void prep_weights(const float* __restrict__ W1l, const float* __restrict__ W1r,
                             const float* __restrict__ W2l, const float* __restrict__ W2r,
                             const float* __restrict__ W3) {
    int i = blockIdx.x * blockDim.x + threadIdx.x;
    if (i >= 5 * 65536) return;
    int m = i >> 16, idx = i & 65535;
    int n = idx >> 8, k = idx & 255;
    const float* W = (m == 0) ? W1l : (m == 1) ? W1r : (m == 2) ? W2l
                   : (m == 3) ? W2r : W3;
    g_wtf[i] = __float2half_rn(W[k * 256 + n]);
}
__global__ void cast_x_kernel(const float* __restrict__ x) {
    size_t i = (size_t)(blockIdx.x * blockDim.x + threadIdx.x) * 4;
    if (i >= (size_t)NN * D) return;
    float4 v = *(const float4*)(x + i);
    *(uint2*)((fp16*)g_xh + i) = make_uint2(pack_h2(v.x, v.y), pack_h2(v.z, v.w));
}

// ---------------- gather aggregation -----------------------------------------
// Reads fp16 features (512B/row); accumulates fp32; writes fp16 mean.
__global__ __launch_bounds__(256)
void aggregate_kernel(const fp16* __restrict__ fh, fp16* __restrict__ outh) {
    int warp = (blockIdx.x * blockDim.x + threadIdx.x) >> 5;
    int lane = threadIdx.x & 31;
    if (warp >= NN) return;
    int deg = g_cnt[warp];
    const int* lst = g_srclist + (size_t)warp * CAP;

    float a[8];
#pragma unroll
    for (int q = 0; q < 8; q++) a[q] = 0.f;

    int nIn = min(deg, CAP);
    for (int base = 0; base < nIn; base += 32) {
        int sv = 0;
        if (base + lane < nIn) sv = lst[base + lane];
        int cnt = min(nIn - base, 32);
#pragma unroll 4
        for (int j = 0; j < cnt; j++) {
            int sj = __shfl_sync(0xffffffffu, sv, j);
            uint4 v = ((const uint4*)(fh + (size_t)sj * D))[lane];
            float2 p;
            p = h2_to_f2(v.x); a[0] += p.x; a[1] += p.y;
            p = h2_to_f2(v.y); a[2] += p.x; a[3] += p.y;
            p = h2_to_f2(v.z); a[4] += p.x; a[5] += p.y;
            p = h2_to_f2(v.w); a[6] += p.x; a[7] += p.y;
        }
    }
    float inv = 1.0f / fmaxf((float)deg, 1.0f);
#pragma unroll
    for (int q = 0; q < 8; q++) a[q] *= inv;

    if (deg > CAP) {   // rare overflow path needs the fp32 partial mean
        float* ad = g_agg + (size_t)warp * D + lane * 8;
        *(float4*)ad       = make_float4(a[0], a[1], a[2], a[3]);
        *(float4*)(ad + 4) = make_float4(a[4], a[5], a[6], a[7]);
    }

    uint4 hv = make_uint4(pack_h2(a[0], a[1]), pack_h2(a[2], a[3]),
                          pack_h2(a[4], a[5]), pack_h2(a[6], a[7]));
    *(uint4*)(outh + (size_t)warp * D + lane * 8) = hv;
}

// overflow fallback: add remaining edges into fp32 agg (reads fp16 feats)
__global__ void ovf_kernel(const fp16* __restrict__ fh) {
    int lane = threadIdx.x & 31;
    int w    = (blockIdx.x * blockDim.x + threadIdx.x) >> 5;
    int nw   = (gridDim.x * blockDim.x) >> 5;
    int n = min(g_novf, MAXOVF);
    for (int e = w; e < n; e += nw) {
        int s = g_ovf[2 * e], d = g_ovf[2 * e + 1];
        float inv = 1.0f / fmaxf((float)g_cnt[d], 1.0f);
        float* ad = g_agg + (size_t)d * D;
        for (int i = lane; i < D; i += 32)
            atomicAdd(ad + i, __half2float(fh[(size_t)s * D + i]) * inv);
    }
}
__global__ void fixrow_kernel(fp16* __restrict__ outh) {
    int lane = threadIdx.x & 31;
    int w    = (blockIdx.x * blockDim.x + threadIdx.x) >> 5;
    int nw   = (gridDim.x * blockDim.x) >> 5;
    int n = min(g_novf, MAXOVF);
    for (int e = w; e < n; e += nw) {
        int d = g_ovf[2 * e + 1];
        const float* src = g_agg + (size_t)d * D;
        for (int c = lane; c < D; c += 32)
            outh[(size_t)d * D + c] = __float2half_rn(src[c]);
    }
}

// ---------------- mma.sync GEMM ----------------------------------------------
// CTA: 128 rows x 128 cols, grid (782, 2), 2 CTAs/SM (4 warps/SMSP).
// 8 warps (4m x 2n), warp tile 32x64.
// C = [relu]( A1@W1' (+ A2@W2') + bias ); plain fp16 operands, fp32 accumulate.
// Smem stage: A | B, each 128 rows x 64 k fp16, row stride 144B (conflict-free).
#define KC     64
#define ROWB   144
#define MAT    18432            // 128 * 144
#define STAGE  (2 * MAT)        // 36864
#define SMEMSZ (2 * STAGE)      // 73728

template<bool DUAL, bool RELU, bool F32OUT, bool F16OUT>
__global__ __launch_bounds__(256, 2)
void mma_gemm(const fp16* __restrict__ a1, const fp16* __restrict__ w1,
              const fp16* __restrict__ a2, const fp16* __restrict__ w2,
              const float* __restrict__ bias,
              float* __restrict__ Cf, fp16* __restrict__ Ch) {
    extern __shared__ char smem[];
    const uint32_t sb = smem_u32(smem);
    const int tid  = threadIdx.x;
    const int wid  = tid >> 5;
    const int lane = tid & 31;
    const int wm   = wid & 3;        // m strip: wm*32
    const int wn   = wid >> 2;       // n strip: wn*64
    const int m0   = blockIdx.x * 128;
    const int n0   = blockIdx.y * 128;

    float acc[2][8][4];
#pragma unroll
    for (int mi = 0; mi < 2; mi++)
#pragma unroll
        for (int ni = 0; ni < 8; ni++)
#pragma unroll
            for (int q = 0; q < 4; q++) acc[mi][ni][q] = 0.f;

    const int nIter = (DUAL ? 2 : 1) * 4;    // K chunks of 64

    auto prefetch = [&](int buf, int it) {
        const int rep   = it >> 2;
        const int kbase = (it & 3) * KC;
        const fp16* A = rep ? a2 : a1;
        const fp16* W = rep ? w2 : w1;
        const uint32_t bb = sb + buf * STAGE;
        // A: 128 rows x 8 chunks(16B) = 1024 slots; B same.
#pragma unroll
        for (int i = 0; i < 4; i++) {
            int q   = tid + i * 256;
            int row = q >> 3, c8 = q & 7;
            uint32_t dsto = (uint32_t)(row * ROWB + c8 * 16);
            int grow = m0 + row;
            int arow = grow < NN ? grow : 0;
            int sz   = grow < NN ? 16 : 0;
            cp16(bb + dsto, A + (size_t)arow * D + kbase + c8 * 8, sz);
            cp16(bb + MAT + dsto, W + (size_t)(n0 + row) * D + kbase + c8 * 8, 16);
        }
    };

    prefetch(0, 0);
    cp_commit();

    const int alr = lane & 15, akh = lane >> 4;                        // A lane map
    const int bnr = lane & 7, bkh = (lane >> 3) & 1, btl = lane >> 4;  // B lane map

    for (int it = 0; it < nIter; it++) {
        if (it + 1 < nIter) { prefetch((it + 1) & 1, it + 1); cp_commit(); cp_wait<1>(); }
        else                { cp_wait<0>(); }
        __syncthreads();

        const uint32_t bb = sb + (it & 1) * STAGE;
        const uint32_t Ab = bb, Bb = bb + MAT;

#pragma unroll
        for (int k16 = 0; k16 < 4; k16++) {
            const uint32_t a_off = (uint32_t)((wm * 32 + alr) * ROWB + (k16 * 16 + akh * 8) * 2);
            const uint32_t b_off = (uint32_t)((wn * 64 + btl * 8 + bnr) * ROWB + (k16 * 16 + bkh * 8) * 2);

            uint32_t a0[4], a1r[4];
            ldsm4(a0,  Ab + a_off);
            ldsm4(a1r, Ab + a_off + 16 * ROWB);

            // B n16-fragments in pairs: both live -> RAW gap >= 4 on each acc.
#pragma unroll
            for (int np = 0; np < 2; np++) {
                uint32_t r0[4], r1[4];
                ldsm4(r0, Bb + b_off + (2 * np)     * 16 * ROWB);
                ldsm4(r1, Bb + b_off + (2 * np + 1) * 16 * ROWB);
                mma16816(acc[0][4 * np + 0], a0,  r0);
                mma16816(acc[0][4 * np + 1], a0,  r0 + 2);
                mma16816(acc[0][4 * np + 2], a0,  r1);
                mma16816(acc[0][4 * np + 3], a0,  r1 + 2);
                mma16816(acc[1][4 * np + 0], a1r, r0);
                mma16816(acc[1][4 * np + 1], a1r, r0 + 2);
                mma16816(acc[1][4 * np + 2], a1r, r1);
                mma16816(acc[1][4 * np + 3], a1r, r1 + 2);
            }
        }
        __syncthreads();
    }

    // -------- epilogue --------
    const int rbase = m0 + wm * 32 + (lane >> 2);
    const int cbase = n0 + wn * 64 + (lane & 3) * 2;
#pragma unroll
    for (int ni = 0; ni < 8; ni++) {
        const int col = cbase + ni * 8;
        const float b0 = bias[col], b1 = bias[col + 1];
#pragma unroll
        for (int mi = 0; mi < 2; mi++) {
#pragma unroll
            for (int rr = 0; rr < 2; rr++) {
                int row = rbase + mi * 16 + rr * 8;
                if (row >= NN) continue;
                float v0 = acc[mi][ni][rr * 2 + 0] + b0;
                float v1 = acc[mi][ni][rr * 2 + 1] + b1;
                if (RELU) { v0 = fmaxf(v0, 0.f); v1 = fmaxf(v1, 0.f); }
                if (F32OUT)
                    *(float2*)(Cf + (size_t)row * D + col) = make_float2(v0, v1);
                if (F16OUT)
                    *(uint32_t*)(Ch + (size_t)row * D + col) = pack_h2(v0, v1);
            }
        }
    }
}

// ---------------- launch ------------------------------------------------------
extern "C" void kernel_launch(void* const* d_in, const int* in_sizes, int n_in,
                              void* d_out, int out_size) {
    const float* x   = (const float*)d_in[0];
    const int*   ei  = (const int*)d_in[1];
    const float* W1l = (const float*)d_in[2];
    const float* b1  = (const float*)d_in[3];
    const float* W1r = (const float*)d_in[4];
    const float* W2l = (const float*)d_in[5];
    const float* b2  = (const float*)d_in[6];
    const float* W2r = (const float*)d_in[7];
    const float* W3  = (const float*)d_in[8];
    const float* b3  = (const float*)d_in[9];
    float* out = (float*)d_out;

    int* cnt;
    fp16 *xh, *ah, *h1h, *h2h, *wtf;
    cudaGetSymbolAddress((void**)&cnt, g_cnt);
    cudaGetSymbolAddress((void**)&xh,  g_xh);
    cudaGetSymbolAddress((void**)&ah,  g_ah);
    cudaGetSymbolAddress((void**)&h1h, g_h1h);
    cudaGetSymbolAddress((void**)&h2h, g_h2h);
    cudaGetSymbolAddress((void**)&wtf, g_wtf);

    cudaFuncSetAttribute(mma_gemm<true,  true,  false, true>,
                         cudaFuncAttributeMaxDynamicSharedMemorySize, SMEMSZ);
    cudaFuncSetAttribute(mma_gemm<false, false, true,  false>,
                         cudaFuncAttributeMaxDynamicSharedMemorySize, SMEMSZ);

    dim3 gemmGrid((NN + 127) / 128, 2);            // (782, 2)
    const int aggBlocks = (NN * 32 + 255) / 256;

    // ---- graph prep ----
    probe_kernel<<<1, 32>>>(ei);
    zero_int_kernel<<<(NN + 255) / 256, 256>>>(cnt, NN);
    build_kernel<<<(NE + 255) / 256, 256>>>(ei);
    prep_weights<<<(5 * 65536 + 255) / 256, 256>>>(W1l, W1r, W2l, W2r, W3);
    cast_x_kernel<<<(NN * D / 4 + 255) / 256, 256>>>(x);

    // ---- layer 1 ----
    aggregate_kernel<<<aggBlocks, 256>>>(xh, ah);
    ovf_kernel<<<32, 256>>>(xh);
    fixrow_kernel<<<16, 256>>>(ah);
    mma_gemm<true, true, false, true><<<gemmGrid, 256, SMEMSZ>>>(
        ah, wtf + 0 * 65536, xh, wtf + 1 * 65536, b1, nullptr, h1h);

    // ---- layer 2 ----
    aggregate_kernel<<<aggBlocks, 256>>>(h1h, ah);
    ovf_kernel<<<32, 256>>>(h1h);
    fixrow_kernel<<<16, 256>>>(ah);
    mma_gemm<true, true, false, true><<<gemmGrid, 256, SMEMSZ>>>(
        ah, wtf + 2 * 65536, h1h, wtf + 3 * 65536, b2, nullptr, h2h);

    // ---- head ----
    mma_gemm<false, false, true, false><<<gemmGrid, 256, SMEMSZ>>>(
        h2h, wtf + 4 * 65536, nullptr, nullptr, b3, out, nullptr);
}

// round 13
// speedup vs baseline: 4.4446x; 1.0324x over previous
#include <cuda_runtime.h>
#include <cuda_fp16.h>
#include <cstdint>

#define NN 100000
#define D  256
#define NE 1600000
#define CAP 128
#define MAXOVF 65536

typedef __half fp16;

// ---------------- scratch (device globals: allocations are forbidden) -------
__device__ float g_agg[(size_t)NN * D];       // fp32 agg (overflow path only)
__device__ fp16  g_xh [(size_t)NN * D];
__device__ fp16  g_ah [(size_t)NN * D];
__device__ fp16  g_h1h[(size_t)NN * D];
__device__ fp16  g_h2h[(size_t)NN * D];
__device__ fp16  g_wtf[5 * 65536];            // transposed weights [N][K], fp16
__device__ int   g_cnt[NN];
__device__ int   g_srclist[(size_t)NN * CAP];
__device__ int   g_ovf[2 * MAXOVF];
__device__ int   g_novf;
__device__ int   g_is64;

// ---------------- helpers ----------------------------------------------------
__device__ __forceinline__ uint32_t smem_u32(const void* p) {
    uint32_t a;
    asm("{ .reg .u64 t; cvta.to.shared.u64 t, %1; cvt.u32.u64 %0, t; }"
        : "=r"(a) : "l"(p));
    return a;
}
__device__ __forceinline__ void cp16(uint32_t dst, const void* src, int sz) {
    asm volatile("cp.async.cg.shared.global [%0], [%1], 16, %2;"
                 :: "r"(dst), "l"(src), "r"(sz) : "memory");
}
__device__ __forceinline__ void cp_commit() {
    asm volatile("cp.async.commit_group;" ::: "memory");
}
template<int N>
__device__ __forceinline__ void cp_wait() {
    asm volatile("cp.async.wait_group %0;" :: "n"(N) : "memory");
}
__device__ __forceinline__ void ldsm4(uint32_t* r, uint32_t addr) {
    asm volatile("ldmatrix.sync.aligned.m8n8.x4.shared.b16 {%0,%1,%2,%3}, [%4];"
                 : "=r"(r[0]), "=r"(r[1]), "=r"(r[2]), "=r"(r[3]) : "r"(addr));
}
__device__ __forceinline__ void mma16816(float* c, const uint32_t* a, const uint32_t* b) {
    asm volatile("mma.sync.aligned.m16n8k16.row.col.f32.f16.f16.f32 "
                 "{%0,%1,%2,%3}, {%4,%5,%6,%7}, {%8,%9}, {%0,%1,%2,%3};"
                 : "+f"(c[0]), "+f"(c[1]), "+f"(c[2]), "+f"(c[3])
                 : "r"(a[0]), "r"(a[1]), "r"(a[2]), "r"(a[3]),
                   "r"(b[0]), "r"(b[1]));
}
__device__ __forceinline__ uint32_t pack_h2(float a, float b) {
    __half2 t = __floats2half2_rn(a, b);
    return *reinterpret_cast<uint32_t*>(&t);
}
__device__ __forceinline__ float2 h2_to_f2(uint32_t u) {
    __half2 h = *reinterpret_cast<__half2*>(&u);
    return __half22float2(h);
}

// ---------------- fused setup -------------------------------------------------
// Blocks partitioned by role:
//   [0, 25000)      cast x -> fp16            (25,000 * 256 * 4 = NN*D elems)
//   [25000, 26280)  weight transpose+cast     (1280 * 256 = 5*65536)
//   [26280, 26671)  zero g_cnt                (391 * 256 >= NN)
//   26671           dtype probe + novf reset
// build_kernel launch boundary orders all of these before use.
#define SETUP_XB   25000
#define SETUP_WB   (SETUP_XB + 1280)
#define SETUP_ZB   (SETUP_WB + 391)
#define SETUP_GRID (SETUP_ZB + 1)

__global__ void setup_kernel(const float* __restrict__ x,
                             const float* __restrict__ W1l, const float* __restrict__ W1r,
                             const float* __restrict__ W2l, const float* __restrict__ W2r,
                             const float* __restrict__ W3,
                             const int* __restrict__ w) {
    int b = blockIdx.x;
    int t = threadIdx.x;
    if (b < SETUP_XB) {
        size_t i = ((size_t)b * 256 + t) * 4;
        float4 v = *(const float4*)(x + i);
        *(uint2*)((fp16*)g_xh + i) = make_uint2(pack_h2(v.x, v.y), pack_h2(v.z, v.w));
    } else if (b < SETUP_WB) {
        int i = (b - SETUP_XB) * 256 + t;
        int m = i >> 16, idx = i & 65535;
        int n = idx >> 8, k = idx & 255;
        const float* W = (m == 0) ? W1l : (m == 1) ? W1r : (m == 2) ? W2l
                       : (m == 3) ? W2r : W3;
        g_wtf[i] = __float2half_rn(W[k * 256 + n]);
    } else if (b < SETUP_ZB) {
        int i = (b - SETUP_WB) * 256 + t;
        if (i < NN) g_cnt[i] = 0;
    } else if (t == 0) {
        int all_zero = 1;
        for (int i = 1; i < 128; i += 2)
            if (w[i] != 0) { all_zero = 0; break; }
        g_is64 = all_zero;
        g_novf = 0;
    }
}

__global__ void build_kernel(const int* __restrict__ w) {
    int e = blockIdx.x * blockDim.x + threadIdx.x;
    if (e >= NE) return;
    int s, d;
    if (g_is64) { s = w[2 * e]; d = w[2 * (NE + e)]; }
    else        { s = w[e];     d = w[NE + e];       }
    int pos = atomicAdd(&g_cnt[d], 1);
    if (pos < CAP) {
        g_srclist[(size_t)d * CAP + pos] = s;
    } else {
        int o = atomicAdd(&g_novf, 1);
        if (o < MAXOVF) { g_ovf[2 * o] = s; g_ovf[2 * o + 1] = d; }
    }
}

// ---------------- gather aggregation -----------------------------------------
// Reads fp16 features (512B/row); accumulates fp32; writes fp16 mean.
__global__ __launch_bounds__(256)
void aggregate_kernel(const fp16* __restrict__ fh, fp16* __restrict__ outh) {
    int warp = (blockIdx.x * blockDim.x + threadIdx.x) >> 5;
    int lane = threadIdx.x & 31;
    if (warp >= NN) return;
    int deg = g_cnt[warp];
    const int* lst = g_srclist + (size_t)warp * CAP;

    float a[8];
#pragma unroll
    for (int q = 0; q < 8; q++) a[q] = 0.f;

    int nIn = min(deg, CAP);
    for (int base = 0; base < nIn; base += 32) {
        int sv = 0;
        if (base + lane < nIn) sv = lst[base + lane];
        int cnt = min(nIn - base, 32);
#pragma unroll 4
        for (int j = 0; j < cnt; j++) {
            int sj = __shfl_sync(0xffffffffu, sv, j);
            uint4 v = ((const uint4*)(fh + (size_t)sj * D))[lane];
            float2 p;
            p = h2_to_f2(v.x); a[0] += p.x; a[1] += p.y;
            p = h2_to_f2(v.y); a[2] += p.x; a[3] += p.y;
            p = h2_to_f2(v.z); a[4] += p.x; a[5] += p.y;
            p = h2_to_f2(v.w); a[6] += p.x; a[7] += p.y;
        }
    }
    float inv = 1.0f / fmaxf((float)deg, 1.0f);
#pragma unroll
    for (int q = 0; q < 8; q++) a[q] *= inv;

    if (deg > CAP) {   // rare overflow path needs the fp32 partial mean
        float* ad = g_agg + (size_t)warp * D + lane * 8;
        *(float4*)ad       = make_float4(a[0], a[1], a[2], a[3]);
        *(float4*)(ad + 4) = make_float4(a[4], a[5], a[6], a[7]);
    }

    uint4 hv = make_uint4(pack_h2(a[0], a[1]), pack_h2(a[2], a[3]),
                          pack_h2(a[4], a[5]), pack_h2(a[6], a[7]));
    *(uint4*)(outh + (size_t)warp * D + lane * 8) = hv;
}

// overflow repair: phase1 adds remaining edges into fp32 agg, phase2 re-casts
// affected rows. Single block so __syncthreads orders the phases. novf==0 in
// practice -> returns immediately.
__global__ void ovffix_kernel(const fp16* __restrict__ fh, fp16* __restrict__ outh) {
    int n = min(g_novf, MAXOVF);
    int lane = threadIdx.x & 31;
    int w    = threadIdx.x >> 5;          // 32 warps
    for (int e = w; e < n; e += 32) {
        int s = g_ovf[2 * e], d = g_ovf[2 * e + 1];
        float inv = 1.0f / fmaxf((float)g_cnt[d], 1.0f);
        float* ad = g_agg + (size_t)d * D;
        for (int i = lane; i < D; i += 32)
            atomicAdd(ad + i, __half2float(fh[(size_t)s * D + i]) * inv);
    }
    __syncthreads();
    for (int e = w; e < n; e += 32) {
        int d = g_ovf[2 * e + 1];
        const float* src = g_agg + (size_t)d * D;
        for (int c = lane; c < D; c += 32)
            outh[(size_t)d * D + c] = __float2half_rn(src[c]);
    }
}

// ---------------- mma.sync GEMM ----------------------------------------------
// CTA: 128 rows x 128 cols, grid (782, 2), 2 CTAs/SM (4 warps/SMSP).
// 8 warps (4m x 2n), warp tile 32x64.
// C = [relu]( A1@W1' (+ A2@W2') + bias ); plain fp16 operands, fp32 accumulate.
// 3-stage cp.async pipeline, one __syncthreads per iteration.
// Smem stage: A | B, each 128 rows x 64 k fp16, row stride 144B (conflict-free).
#define KC     64
#define ROWB   144
#define MAT    18432            // 128 * 144
#define STAGE  (2 * MAT)        // 36864
#define SMEMSZ (3 * STAGE)      // 110592

template<bool DUAL, bool RELU, bool F32OUT, bool F16OUT>
__global__ __launch_bounds__(256, 2)
void mma_gemm(const fp16* __restrict__ a1, const fp16* __restrict__ w1,
              const fp16* __restrict__ a2, const fp16* __restrict__ w2,
              const float* __restrict__ bias,
              float* __restrict__ Cf, fp16* __restrict__ Ch) {
    extern __shared__ char smem[];
    const uint32_t sb = smem_u32(smem);
    const int tid  = threadIdx.x;
    const int wid  = tid >> 5;
    const int lane = tid & 31;
    const int wm   = wid & 3;        // m strip: wm*32
    const int wn   = wid >> 2;       // n strip: wn*64
    const int m0   = blockIdx.x * 128;
    const int n0   = blockIdx.y * 128;

    float acc[2][8][4];
#pragma unroll
    for (int mi = 0; mi < 2; mi++)
#pragma unroll
        for (int ni = 0; ni < 8; ni++)
#pragma unroll
            for (int q = 0; q < 4; q++) acc[mi][ni][q] = 0.f;

    const int nIter = (DUAL ? 2 : 1) * 4;    // K chunks of 64

    auto prefetch = [&](int buf, int it) {
        const int rep   = it >> 2;
        const int kbase = (it & 3) * KC;
        const fp16* A = rep ? a2 : a1;
        const fp16* W = rep ? w2 : w1;
        const uint32_t bb = sb + buf * STAGE;
        // A: 128 rows x 8 chunks(16B) = 1024 slots; B same.
#pragma unroll
        for (int i = 0; i < 4; i++) {
            int q   = tid + i * 256;
            int row = q >> 3, c8 = q & 7;
            uint32_t dsto = (uint32_t)(row * ROWB + c8 * 16);
            int grow = m0 + row;
            int arow = grow < NN ? grow : 0;
            int sz   = grow < NN ? 16 : 0;
            cp16(bb + dsto, A + (size_t)arow * D + kbase + c8 * 8, sz);
            cp16(bb + MAT + dsto, W + (size_t)(n0 + row) * D + kbase + c8 * 8, 16);
        }
    };

    prefetch(0, 0);
    cp_commit();
    prefetch(1, 1);
    cp_commit();

    const int alr = lane & 15, akh = lane >> 4;                        // A lane map
    const int bnr = lane & 7, bkh = (lane >> 3) & 1, btl = lane >> 4;  // B lane map

    int buf = 0;
    for (int it = 0; it < nIter; it++) {
        if (it + 1 < nIter) cp_wait<1>();     // stage `it` landed
        else                cp_wait<0>();
        __syncthreads();                      // all warps done with stage it-1's buffer
        if (it + 2 < nIter) { prefetch((it + 2) % 3, it + 2); cp_commit(); }

        const uint32_t bb = sb + buf * STAGE;
        const uint32_t Ab = bb, Bb = bb + MAT;
        buf = (buf + 1 == 3) ? 0 : buf + 1;

#pragma unroll
        for (int k16 = 0; k16 < 4; k16++) {
            const uint32_t a_off = (uint32_t)((wm * 32 + alr) * ROWB + (k16 * 16 + akh * 8) * 2);
            const uint32_t b_off = (uint32_t)((wn * 64 + btl * 8 + bnr) * ROWB + (k16 * 16 + bkh * 8) * 2);

            uint32_t a0[4], a1r[4];
            ldsm4(a0,  Ab + a_off);
            ldsm4(a1r, Ab + a_off + 16 * ROWB);

            // B n16-fragments in pairs: both live -> RAW gap >= 4 on each acc.
#pragma unroll
            for (int np = 0; np < 2; np++) {
                uint32_t r0[4], r1[4];
                ldsm4(r0, Bb + b_off + (2 * np)     * 16 * ROWB);
                ldsm4(r1, Bb + b_off + (2 * np + 1) * 16 * ROWB);
                mma16816(acc[0][4 * np + 0], a0,  r0);
                mma16816(acc[0][4 * np + 1], a0,  r0 + 2);
                mma16816(acc[0][4 * np + 2], a0,  r1);
                mma16816(acc[0][4 * np + 3], a0,  r1 + 2);
                mma16816(acc[1][4 * np + 0], a1r, r0);
                mma16816(acc[1][4 * np + 1], a1r, r0 + 2);
                mma16816(acc[1][4 * np + 2], a1r, r1);
                mma16816(acc[1][4 * np + 3], a1r, r1 + 2);
            }
        }
    }

    // -------- epilogue --------
    const int rbase = m0 + wm * 32 + (lane >> 2);
    const int cbase = n0 + wn * 64 + (lane & 3) * 2;
#pragma unroll
    for (int ni = 0; ni < 8; ni++) {
        const int col = cbase + ni * 8;
        const float b0 = bias[col], b1 = bias[col + 1];
#pragma unroll
        for (int mi = 0; mi < 2; mi++) {
#pragma unroll
            for (int rr = 0; rr < 2; rr++) {
                int row = rbase + mi * 16 + rr * 8;
                if (row >= NN) continue;
                float v0 = acc[mi][ni][rr * 2 + 0] + b0;
                float v1 = acc[mi][ni][rr * 2 + 1] + b1;
                if (RELU) { v0 = fmaxf(v0, 0.f); v1 = fmaxf(v1, 0.f); }
                if (F32OUT)
                    *(float2*)(Cf + (size_t)row * D + col) = make_float2(v0, v1);
                if (F16OUT)
                    *(uint32_t*)(Ch + (size_t)row * D + col) = pack_h2(v0, v1);
            }
        }
    }
}

// ---------------- launch ------------------------------------------------------
extern "C" void kernel_launch(void* const* d_in, const int* in_sizes, int n_in,
                              void* d_out, int out_size) {
    const float* x   = (const float*)d_in[0];
    const int*   ei  = (const int*)d_in[1];
    const float* W1l = (const float*)d_in[2];
    const float* b1  = (const float*)d_in[3];
    const float* W1r = (const float*)d_in[4];
    const float* W2l = (const float*)d_in[5];
    const float* b2  = (const float*)d_in[6];
    const float* W2r = (const float*)d_in[7];
    const float* W3  = (const float*)d_in[8];
    const float* b3  = (const float*)d_in[9];
    float* out = (float*)d_out;

    fp16 *xh, *ah, *h1h, *h2h, *wtf;
    cudaGetSymbolAddress((void**)&xh,  g_xh);
    cudaGetSymbolAddress((void**)&ah,  g_ah);
    cudaGetSymbolAddress((void**)&h1h, g_h1h);
    cudaGetSymbolAddress((void**)&h2h, g_h2h);
    cudaGetSymbolAddress((void**)&wtf, g_wtf);

    cudaFuncSetAttribute(mma_gemm<true,  true,  false, true>,
                         cudaFuncAttributeMaxDynamicSharedMemorySize, SMEMSZ);
    cudaFuncSetAttribute(mma_gemm<false, false, true,  false>,
                         cudaFuncAttributeMaxDynamicSharedMemorySize, SMEMSZ);

    dim3 gemmGrid((NN + 127) / 128, 2);            // (782, 2)
    const int aggBlocks = (NN * 32 + 255) / 256;

    // ---- fused prep (cast x | transpose weights | zero cnt | probe) ----
    setup_kernel<<<SETUP_GRID, 256>>>(x, W1l, W1r, W2l, W2r, W3, ei);
    build_kernel<<<(NE + 255) / 256, 256>>>(ei);

    // ---- layer 1 ----
    aggregate_kernel<<<aggBlocks, 256>>>(xh, ah);
    ovffix_kernel<<<1, 1024>>>(xh, ah);
    mma_gemm<true, true, false, true><<<gemmGrid, 256, SMEMSZ>>>(
        ah, wtf + 0 * 65536, xh, wtf + 1 * 65536, b1, nullptr, h1h);

    // ---- layer 2 ----
    aggregate_kernel<<<aggBlocks, 256>>>(h1h, ah);
    ovffix_kernel<<<1, 1024>>>(h1h, ah);
    mma_gemm<true, true, false, true><<<gemmGrid, 256, SMEMSZ>>>(
        ah, wtf + 2 * 65536, h1h, wtf + 3 * 65536, b2, nullptr, h2h);

    // ---- head ----
    mma_gemm<false, false, true, false><<<gemmGrid, 256, SMEMSZ>>>(
        h2h, wtf + 4 * 65536, nullptr, nullptr, b3, out, nullptr);
}

// round 14
// speedup vs baseline: 4.4908x; 1.0104x over previous
#include <cuda_runtime.h>
#include <cuda_fp16.h>
#include <cstdint>

#define NN 100000
#define D  256
#define NE 1600000
#define CAP 128
#define MAXOVF 65536

typedef __half fp16;

// ---------------- scratch (device globals: allocations are forbidden) -------
__device__ fp16  g_xh [(size_t)NN * D];
__device__ fp16  g_ah [(size_t)NN * D];
__device__ fp16  g_h1h[(size_t)NN * D];
__device__ fp16  g_h2h[(size_t)NN * D];
__device__ fp16  g_wtf[5 * 65536];            // transposed weights [N][K], fp16
__device__ int   g_cnt[NN];
__device__ int   g_srclist[(size_t)NN * CAP];
__device__ int   g_ovf[2 * MAXOVF];
__device__ int   g_novf;
__device__ int   g_is64;

// ---------------- helpers ----------------------------------------------------
__device__ __forceinline__ uint32_t smem_u32(const void* p) {
    uint32_t a;
    asm("{ .reg .u64 t; cvta.to.shared.u64 t, %1; cvt.u32.u64 %0, t; }"
        : "=r"(a) : "l"(p));
    return a;
}
__device__ __forceinline__ void cp16(uint32_t dst, const void* src, int sz) {
    asm volatile("cp.async.cg.shared.global [%0], [%1], 16, %2;"
                 :: "r"(dst), "l"(src), "r"(sz) : "memory");
}
__device__ __forceinline__ void cp_commit() {
    asm volatile("cp.async.commit_group;" ::: "memory");
}
template<int N>
__device__ __forceinline__ void cp_wait() {
    asm volatile("cp.async.wait_group %0;" :: "n"(N) : "memory");
}
__device__ __forceinline__ void ldsm4(uint32_t* r, uint32_t addr) {
    asm volatile("ldmatrix.sync.aligned.m8n8.x4.shared.b16 {%0,%1,%2,%3}, [%4];"
                 : "=r"(r[0]), "=r"(r[1]), "=r"(r[2]), "=r"(r[3]) : "r"(addr));
}
__device__ __forceinline__ void mma16816(float* c, const uint32_t* a, const uint32_t* b) {
    asm volatile("mma.sync.aligned.m16n8k16.row.col.f32.f16.f16.f32 "
                 "{%0,%1,%2,%3}, {%4,%5,%6,%7}, {%8,%9}, {%0,%1,%2,%3};"
                 : "+f"(c[0]), "+f"(c[1]), "+f"(c[2]), "+f"(c[3])
                 : "r"(a[0]), "r"(a[1]), "r"(a[2]), "r"(a[3]),
                   "r"(b[0]), "r"(b[1]));
}
__device__ __forceinline__ uint32_t pack_h2(float a, float b) {
    __half2 t = __floats2half2_rn(a, b);
    return *reinterpret_cast<uint32_t*>(&t);
}
__device__ __forceinline__ float2 h2_to_f2(uint32_t u) {
    __half2 h = *reinterpret_cast<__half2*>(&u);
    return __half22float2(h);
}

// ---------------- fused setup -------------------------------------------------
// Blocks partitioned by role:
//   [0, 25000)      cast x -> fp16            (25,000 * 256 * 4 = NN*D elems)
//   [25000, 26280)  weight transpose+cast     (1280 * 256 = 5*65536)
//   [26280, 26671)  zero g_cnt                (391 * 256 >= NN)
//   26671           dtype probe + novf reset
// build_kernel launch boundary orders all of these before use.
#define SETUP_XB   25000
#define SETUP_WB   (SETUP_XB + 1280)
#define SETUP_ZB   (SETUP_WB + 391)
#define SETUP_GRID (SETUP_ZB + 1)

__global__ void setup_kernel(const float* __restrict__ x,
                             const float* __restrict__ W1l, const float* __restrict__ W1r,
                             const float* __restrict__ W2l, const float* __restrict__ W2r,
                             const float* __restrict__ W3,
                             const int* __restrict__ w) {
    int b = blockIdx.x;
    int t = threadIdx.x;
    if (b < SETUP_XB) {
        size_t i = ((size_t)b * 256 + t) * 4;
        float4 v = *(const float4*)(x + i);
        *(uint2*)((fp16*)g_xh + i) = make_uint2(pack_h2(v.x, v.y), pack_h2(v.z, v.w));
    } else if (b < SETUP_WB) {
        int i = (b - SETUP_XB) * 256 + t;
        int m = i >> 16, idx = i & 65535;
        int n = idx >> 8, k = idx & 255;
        const float* W = (m == 0) ? W1l : (m == 1) ? W1r : (m == 2) ? W2l
                       : (m == 3) ? W2r : W3;
        g_wtf[i] = __float2half_rn(W[k * 256 + n]);
    } else if (b < SETUP_ZB) {
        int i = (b - SETUP_WB) * 256 + t;
        if (i < NN) g_cnt[i] = 0;
    } else if (t == 0) {
        int all_zero = 1;
        for (int i = 1; i < 128; i += 2)
            if (w[i] != 0) { all_zero = 0; break; }
        g_is64 = all_zero;
        g_novf = 0;
    }
}

__global__ void build_kernel(const int* __restrict__ w) {
    int e = blockIdx.x * blockDim.x + threadIdx.x;
    if (e >= NE) return;
    int s, d;
    if (g_is64) { s = w[2 * e]; d = w[2 * (NE + e)]; }
    else        { s = w[e];     d = w[NE + e];       }
    int pos = atomicAdd(&g_cnt[d], 1);
    if (pos < CAP) {
        g_srclist[(size_t)d * CAP + pos] = s;
    } else {
        int o = atomicAdd(&g_novf, 1);
        if (o < MAXOVF) { g_ovf[2 * o] = s; g_ovf[2 * o + 1] = d; }
    }
}

// ---------------- gather aggregation -----------------------------------------
// Reads fp16 features (512B/row); accumulates fp32; writes fp16 mean.
// Overflow (deg > CAP) handled in-kernel: the owning warp scans g_ovf for its
// own dst and accumulates those sources too. Exact; never taken for this graph.
__global__ __launch_bounds__(256)
void aggregate_kernel(const fp16* __restrict__ fh, fp16* __restrict__ outh) {
    int warp = (blockIdx.x * blockDim.x + threadIdx.x) >> 5;
    int lane = threadIdx.x & 31;
    if (warp >= NN) return;
    int deg = g_cnt[warp];
    const int* lst = g_srclist + (size_t)warp * CAP;

    float a[8];
#pragma unroll
    for (int q = 0; q < 8; q++) a[q] = 0.f;

    int nIn = min(deg, CAP);
    for (int base = 0; base < nIn; base += 32) {
        int sv = 0;
        if (base + lane < nIn) sv = lst[base + lane];
        int cnt = min(nIn - base, 32);
#pragma unroll 4
        for (int j = 0; j < cnt; j++) {
            int sj = __shfl_sync(0xffffffffu, sv, j);
            uint4 v = ((const uint4*)(fh + (size_t)sj * D))[lane];
            float2 p;
            p = h2_to_f2(v.x); a[0] += p.x; a[1] += p.y;
            p = h2_to_f2(v.y); a[2] += p.x; a[3] += p.y;
            p = h2_to_f2(v.z); a[4] += p.x; a[5] += p.y;
            p = h2_to_f2(v.w); a[6] += p.x; a[7] += p.y;
        }
    }

    if (deg > CAP) {   // rare exact-repair path: pull my edges from g_ovf
        int n = min(g_novf, MAXOVF);
        for (int e = 0; e < n; e++) {
            if (g_ovf[2 * e + 1] == warp) {
                int sj = g_ovf[2 * e];
                uint4 v = ((const uint4*)(fh + (size_t)sj * D))[lane];
                float2 p;
                p = h2_to_f2(v.x); a[0] += p.x; a[1] += p.y;
                p = h2_to_f2(v.y); a[2] += p.x; a[3] += p.y;
                p = h2_to_f2(v.z); a[4] += p.x; a[5] += p.y;
                p = h2_to_f2(v.w); a[6] += p.x; a[7] += p.y;
            }
        }
    }

    float inv = 1.0f / fmaxf((float)deg, 1.0f);
#pragma unroll
    for (int q = 0; q < 8; q++) a[q] *= inv;

    uint4 hv = make_uint4(pack_h2(a[0], a[1]), pack_h2(a[2], a[3]),
                          pack_h2(a[4], a[5]), pack_h2(a[6], a[7]));
    *(uint4*)(outh + (size_t)warp * D + lane * 8) = hv;
}

// ---------------- mma.sync GEMM ----------------------------------------------
// CTA: 128 rows x 128 cols, grid (782, 2), 2 CTAs/SM (4 warps/SMSP).
// 8 warps (4m x 2n), warp tile 32x64.
// C = [relu]( A1@W1' (+ A2@W2') + bias ); plain fp16 operands, fp32 accumulate.
// 3-stage cp.async pipeline, one __syncthreads per iteration.
// Smem stage: A | B, each 128 rows x 64 k fp16, row stride 144B (conflict-free).
#define KC     64
#define ROWB   144
#define MAT    18432            // 128 * 144
#define STAGE  (2 * MAT)        // 36864
#define SMEMSZ (3 * STAGE)      // 110592

template<bool DUAL, bool RELU, bool F32OUT, bool F16OUT>
__global__ __launch_bounds__(256, 2)
void mma_gemm(const fp16* __restrict__ a1, const fp16* __restrict__ w1,
              const fp16* __restrict__ a2, const fp16* __restrict__ w2,
              const float* __restrict__ bias,
              float* __restrict__ Cf, fp16* __restrict__ Ch) {
    extern __shared__ char smem[];
    const uint32_t sb = smem_u32(smem);
    const int tid  = threadIdx.x;
    const int wid  = tid >> 5;
    const int lane = tid & 31;
    const int wm   = wid & 3;        // m strip: wm*32
    const int wn   = wid >> 2;       // n strip: wn*64
    const int m0   = blockIdx.x * 128;
    const int n0   = blockIdx.y * 128;

    float acc[2][8][4];
#pragma unroll
    for (int mi = 0; mi < 2; mi++)
#pragma unroll
        for (int ni = 0; ni < 8; ni++)
#pragma unroll
            for (int q = 0; q < 4; q++) acc[mi][ni][q] = 0.f;

    const int nIter = (DUAL ? 2 : 1) * 4;    // K chunks of 64

    auto prefetch = [&](int buf, int it) {
        const int rep   = it >> 2;
        const int kbase = (it & 3) * KC;
        const fp16* A = rep ? a2 : a1;
        const fp16* W = rep ? w2 : w1;
        const uint32_t bb = sb + buf * STAGE;
        // A: 128 rows x 8 chunks(16B) = 1024 slots; B same.
#pragma unroll
        for (int i = 0; i < 4; i++) {
            int q   = tid + i * 256;
            int row = q >> 3, c8 = q & 7;
            uint32_t dsto = (uint32_t)(row * ROWB + c8 * 16);
            int grow = m0 + row;
            int arow = grow < NN ? grow : 0;
            int sz   = grow < NN ? 16 : 0;
            cp16(bb + dsto, A + (size_t)arow * D + kbase + c8 * 8, sz);
            cp16(bb + MAT + dsto, W + (size_t)(n0 + row) * D + kbase + c8 * 8, 16);
        }
    };

    prefetch(0, 0);
    cp_commit();
    prefetch(1, 1);
    cp_commit();

    const int alr = lane & 15, akh = lane >> 4;                        // A lane map
    const int bnr = lane & 7, bkh = (lane >> 3) & 1, btl = lane >> 4;  // B lane map

    int buf = 0;
    for (int it = 0; it < nIter; it++) {
        if (it + 1 < nIter) cp_wait<1>();     // stage `it` landed
        else                cp_wait<0>();
        __syncthreads();                      // all warps done with stage it-1's buffer
        if (it + 2 < nIter) { prefetch((it + 2) % 3, it + 2); cp_commit(); }

        const uint32_t bb = sb + buf * STAGE;
        const uint32_t Ab = bb, Bb = bb + MAT;
        buf = (buf + 1 == 3) ? 0 : buf + 1;

#pragma unroll
        for (int k16 = 0; k16 < 4; k16++) {
            const uint32_t a_off = (uint32_t)((wm * 32 + alr) * ROWB + (k16 * 16 + akh * 8) * 2);
            const uint32_t b_off = (uint32_t)((wn * 64 + btl * 8 + bnr) * ROWB + (k16 * 16 + bkh * 8) * 2);

            uint32_t a0[4], a1r[4];
            ldsm4(a0,  Ab + a_off);
            ldsm4(a1r, Ab + a_off + 16 * ROWB);

            // B n16-fragments in pairs: both live -> RAW gap >= 4 on each acc.
#pragma unroll
            for (int np = 0; np < 2; np++) {
                uint32_t r0[4], r1[4];
                ldsm4(r0, Bb + b_off + (2 * np)     * 16 * ROWB);
                ldsm4(r1, Bb + b_off + (2 * np + 1) * 16 * ROWB);
                mma16816(acc[0][4 * np + 0], a0,  r0);
                mma16816(acc[0][4 * np + 1], a0,  r0 + 2);
                mma16816(acc[0][4 * np + 2], a0,  r1);
                mma16816(acc[0][4 * np + 3], a0,  r1 + 2);
                mma16816(acc[1][4 * np + 0], a1r, r0);
                mma16816(acc[1][4 * np + 1], a1r, r0 + 2);
                mma16816(acc[1][4 * np + 2], a1r, r1);
                mma16816(acc[1][4 * np + 3], a1r, r1 + 2);
            }
        }
    }

    // -------- epilogue --------
    const int rbase = m0 + wm * 32 + (lane >> 2);
    const int cbase = n0 + wn * 64 + (lane & 3) * 2;
#pragma unroll
    for (int ni = 0; ni < 8; ni++) {
        const int col = cbase + ni * 8;
        const float b0 = bias[col], b1 = bias[col + 1];
#pragma unroll
        for (int mi = 0; mi < 2; mi++) {
#pragma unroll
            for (int rr = 0; rr < 2; rr++) {
                int row = rbase + mi * 16 + rr * 8;
                if (row >= NN) continue;
                float v0 = acc[mi][ni][rr * 2 + 0] + b0;
                float v1 = acc[mi][ni][rr * 2 + 1] + b1;
                if (RELU) { v0 = fmaxf(v0, 0.f); v1 = fmaxf(v1, 0.f); }
                if (F32OUT)
                    *(float2*)(Cf + (size_t)row * D + col) = make_float2(v0, v1);
                if (F16OUT)
                    *(uint32_t*)(Ch + (size_t)row * D + col) = pack_h2(v0, v1);
            }
        }
    }
}

// ---------------- launch ------------------------------------------------------
extern "C" void kernel_launch(void* const* d_in, const int* in_sizes, int n_in,
                              void* d_out, int out_size) {
    const float* x   = (const float*)d_in[0];
    const int*   ei  = (const int*)d_in[1];
    const float* W1l = (const float*)d_in[2];
    const float* b1  = (const float*)d_in[3];
    const float* W1r = (const float*)d_in[4];
    const float* W2l = (const float*)d_in[5];
    const float* b2  = (const float*)d_in[6];
    const float* W2r = (const float*)d_in[7];
    const float* W3  = (const float*)d_in[8];
    const float* b3  = (const float*)d_in[9];
    float* out = (float*)d_out;

    fp16 *xh, *ah, *h1h, *h2h, *wtf;
    cudaGetSymbolAddress((void**)&xh,  g_xh);
    cudaGetSymbolAddress((void**)&ah,  g_ah);
    cudaGetSymbolAddress((void**)&h1h, g_h1h);
    cudaGetSymbolAddress((void**)&h2h, g_h2h);
    cudaGetSymbolAddress((void**)&wtf, g_wtf);

    cudaFuncSetAttribute(mma_gemm<true,  true,  false, true>,
                         cudaFuncAttributeMaxDynamicSharedMemorySize, SMEMSZ);
    cudaFuncSetAttribute(mma_gemm<false, false, true,  false>,
                         cudaFuncAttributeMaxDynamicSharedMemorySize, SMEMSZ);

    dim3 gemmGrid((NN + 127) / 128, 2);            // (782, 2)
    const int aggBlocks = (NN * 32 + 255) / 256;

    // ---- fused prep (cast x | transpose weights | zero cnt | probe) ----
    setup_kernel<<<SETUP_GRID, 256>>>(x, W1l, W1r, W2l, W2r, W3, ei);
    build_kernel<<<(NE + 255) / 256, 256>>>(ei);

    // ---- layer 1 ----
    aggregate_kernel<<<aggBlocks, 256>>>(xh, ah);
    mma_gemm<true, true, false, true><<<gemmGrid, 256, SMEMSZ>>>(
        ah, wtf + 0 * 65536, xh, wtf + 1 * 65536, b1, nullptr, h1h);

    // ---- layer 2 ----
    aggregate_kernel<<<aggBlocks, 256>>>(h1h, ah);
    mma_gemm<true, true, false, true><<<gemmGrid, 256, SMEMSZ>>>(
        ah, wtf + 2 * 65536, h1h, wtf + 3 * 65536, b2, nullptr, h2h);

    // ---- head ----
    mma_gemm<false, false, true, false><<<gemmGrid, 256, SMEMSZ>>>(
        h2h, wtf + 4 * 65536, nullptr, nullptr, b3, out, nullptr);
}